// round 14
// baseline (speedup 1.0000x reference)
#include <cuda_runtime.h>
#include <cuda_bf16.h>
#include <cstdint>
#include <cstddef>

#define Bq   2
#define Tq   2048
#define Dq   1024
#define Hq   16
#define DKq  64
#define Mq   (Bq*Tq)     // 4096

// ---------------- scratch (device globals: allocation-free) ----------------
__device__ __align__(16) __nv_bfloat16 g_Ahi[Mq * Dq];
__device__ __align__(16) __nv_bfloat16 g_Alo[Mq * Dq];
__device__ __align__(16) __nv_bfloat16 g_Whi[4][Dq * Dq];   // transposed [n][k]
__device__ __align__(16) __nv_bfloat16 g_Wlo[4][Dq * Dq];
__device__ __align__(16) __nv_bfloat16 g_Qh[Mq * Dq];
__device__ __align__(16) __nv_bfloat16 g_Ql[Mq * Dq];
__device__ __align__(16) __nv_bfloat16 g_Kh[Mq * Dq];
__device__ __align__(16) __nv_bfloat16 g_Kl[Mq * Dq];
__device__ __align__(16) __nv_bfloat16 g_Vh[Mq * Dq];
__device__ __align__(16) __nv_bfloat16 g_Vl[Mq * Dq];
__device__ __align__(16) __nv_bfloat16 g_AOh[Mq * Dq];
__device__ __align__(16) __nv_bfloat16 g_AOl[Mq * Dq];

// ---------------------------------------------------------------------------
__device__ __forceinline__ uint32_t smem_u32(const void* p) {
    uint32_t a;
    asm("{ .reg .u64 t; cvta.to.shared.u64 t, %1; cvt.u32.u64 %0, t; }" : "=r"(a) : "l"(p));
    return a;
}
__device__ __forceinline__ void cp_async16(uint32_t saddr, const void* gaddr) {
    asm volatile("cp.async.cg.shared.global [%0], [%1], 16;" :: "r"(saddr), "l"(gaddr));
}
__device__ __forceinline__ void ldsm_x4(uint32_t* r, uint32_t saddr) {
    asm volatile("ldmatrix.sync.aligned.m8n8.x4.shared.b16 {%0,%1,%2,%3}, [%4];"
                 : "=r"(r[0]), "=r"(r[1]), "=r"(r[2]), "=r"(r[3]) : "r"(saddr));
}
__device__ __forceinline__ void ldsm_x4_t(uint32_t* r, uint32_t saddr) {
    asm volatile("ldmatrix.sync.aligned.m8n8.x4.trans.shared.b16 {%0,%1,%2,%3}, [%4];"
                 : "=r"(r[0]), "=r"(r[1]), "=r"(r[2]), "=r"(r[3]) : "r"(saddr));
}
__device__ __forceinline__ void mma16816(float* d, const uint32_t* a, uint32_t b0, uint32_t b1) {
    asm volatile(
        "mma.sync.aligned.m16n8k16.row.col.f32.bf16.bf16.f32 "
        "{%0,%1,%2,%3}, {%4,%5,%6,%7}, {%8,%9}, {%0,%1,%2,%3};"
        : "+f"(d[0]), "+f"(d[1]), "+f"(d[2]), "+f"(d[3])
        : "r"(a[0]), "r"(a[1]), "r"(a[2]), "r"(a[3]), "r"(b0), "r"(b1));
}
__device__ __forceinline__ uint32_t pack_bf16x2(float a, float b) {
    __nv_bfloat162 t = __halves2bfloat162(__float2bfloat16(a), __float2bfloat16(b));
    return *(uint32_t*)&t;
}

// ---------------------------------------------------------------------------
__global__ void split_kernel(const float* __restrict__ src,
                             __nv_bfloat16* __restrict__ hi,
                             __nv_bfloat16* __restrict__ lo, int n)
{
    int i = (blockIdx.x * blockDim.x + threadIdx.x) * 4;
    if (i >= n) return;
    float4 v = *(const float4*)(src + i);
    __nv_bfloat16 h0 = __float2bfloat16(v.x), h1 = __float2bfloat16(v.y);
    __nv_bfloat16 h2 = __float2bfloat16(v.z), h3 = __float2bfloat16(v.w);
    __nv_bfloat16 l0 = __float2bfloat16(v.x - __bfloat162float(h0));
    __nv_bfloat16 l1 = __float2bfloat16(v.y - __bfloat162float(h1));
    __nv_bfloat16 l2 = __float2bfloat16(v.z - __bfloat162float(h2));
    __nv_bfloat16 l3 = __float2bfloat16(v.w - __bfloat162float(h3));
    ((__nv_bfloat162*)(hi + i))[0] = __halves2bfloat162(h0, h1);
    ((__nv_bfloat162*)(hi + i))[1] = __halves2bfloat162(h2, h3);
    ((__nv_bfloat162*)(lo + i))[0] = __halves2bfloat162(l0, l1);
    ((__nv_bfloat162*)(lo + i))[1] = __halves2bfloat162(l2, l3);
}

__global__ void transpose_split4_kernel(const float* __restrict__ W0,
                                        const float* __restrict__ W1,
                                        const float* __restrict__ W2,
                                        const float* __restrict__ W3,
                                        __nv_bfloat16* __restrict__ hi,
                                        __nv_bfloat16* __restrict__ lo)
{
    __shared__ float tile[32][33];
    const int wsel = blockIdx.z;
    const float* W = (wsel == 0) ? W0 : (wsel == 1) ? W1 : (wsel == 2) ? W2 : W3;
    __nv_bfloat16* hp = hi + (size_t)wsel * Dq * Dq;
    __nv_bfloat16* lp = lo + (size_t)wsel * Dq * Dq;
    int n0 = blockIdx.x * 32, k0 = blockIdx.y * 32;
    int x = threadIdx.x, y = threadIdx.y;
#pragma unroll
    for (int r = 0; r < 32; r += 8)
        tile[y + r][x] = W[(size_t)(k0 + y + r) * Dq + n0 + x];
    __syncthreads();
#pragma unroll
    for (int r = 0; r < 32; r += 8) {
        float v = tile[x][y + r];
        __nv_bfloat16 h = __float2bfloat16(v);
        hp[(size_t)(n0 + y + r) * Dq + k0 + x] = h;
        lp[(size_t)(n0 + y + r) * Dq + k0 + x] = __float2bfloat16(v - __bfloat162float(h));
    }
}

// ---------------------------------------------------------------------------
// Fused-split GEMM (round-13 config, measured best): CTA 64x64, 4 warps,
// BK=32, 2-stage cp.async, occ 5.
// ---------------------------------------------------------------------------
#define GSTAGE 20480
#define GEMM_SMEM (2 * GSTAGE)

template<int MODE>
__global__ void __launch_bounds__(128, 5)
gemm_mma(const __nv_bfloat16* __restrict__ Ah, const __nv_bfloat16* __restrict__ Al,
         const __nv_bfloat16* __restrict__ Bh, const __nv_bfloat16* __restrict__ Bl,
         const float* __restrict__ bias0, const float* __restrict__ bias1,
         const float* __restrict__ bias2,
         float* __restrict__ Cf,
         __nv_bfloat16* __restrict__ O0h, __nv_bfloat16* __restrict__ O0l,
         __nv_bfloat16* __restrict__ O1h, __nv_bfloat16* __restrict__ O1l,
         __nv_bfloat16* __restrict__ O2h, __nv_bfloat16* __restrict__ O2l)
{
    extern __shared__ char smc[];
    const uint32_t smb = smem_u32(smc);
    const int t = threadIdx.x, lane = t & 31, wid = t >> 5;
    const int wm = wid >> 1, wn = wid & 1;
    const int m0 = blockIdx.y * 64, n0 = blockIdx.x * 64;

    float acc[2][4][4];
#pragma unroll
    for (int i = 0; i < 2; i++)
#pragma unroll
        for (int j = 0; j < 4; j++)
#pragma unroll
            for (int k = 0; k < 4; k++) acc[i][j][k] = 0.f;

    const __nv_bfloat16* Amats[2] = { Ah + (size_t)m0 * Dq, Al + (size_t)m0 * Dq };
    const __nv_bfloat16* Bmats[2] = { Bh + (size_t)n0 * Dq, Bl + (size_t)n0 * Dq };

    auto issue = [&](int c) {
        const uint32_t base = smb + (uint32_t)(c & 1) * GSTAGE;
        const int kk = c * 32;
#pragma unroll
        for (int m = 0; m < 2; ++m) {
            const __nv_bfloat16* s = Amats[m] + kk;
#pragma unroll
            for (int it = 0; it < 2; ++it) {
                int idx = t + it * 128;
                int r = idx >> 2, seg = idx & 3;
                cp_async16(base + m * 5120 + r * 80 + seg * 16,
                           s + (size_t)r * Dq + seg * 8);
            }
        }
#pragma unroll
        for (int m = 0; m < 2; ++m) {
            const __nv_bfloat16* s = Bmats[m] + kk;
#pragma unroll
            for (int it = 0; it < 2; ++it) {
                int idx = t + it * 128;
                int r = idx >> 2, seg = idx & 3;
                cp_async16(base + 10240 + m * 5120 + r * 80 + seg * 16,
                           s + (size_t)r * Dq + seg * 8);
            }
        }
        asm volatile("cp.async.commit_group;" ::: "memory");
    };

    issue(0);

    const int arow = wm * 32 + (lane & 15);
    const int aco  = (lane >> 4) * 8;
    const int brow = wn * 32 + ((lane >> 4) & 1) * 8 + (lane & 7);
    const int bco  = ((lane >> 3) & 1) * 8;

    for (int c = 0; c < 32; ++c) {
        asm volatile("cp.async.wait_group 0;" ::: "memory");
        __syncthreads();
        if (c + 1 < 32) issue(c + 1);

        const uint32_t bAh = smb + (uint32_t)(c & 1) * GSTAGE;
        const uint32_t bAl = bAh + 5120, bBh = bAh + 10240, bBl = bAh + 15360;

#pragma unroll
        for (int ks = 0; ks < 2; ++ks) {
            const int kof  = (ks * 16 + aco) * 2;
            const int kofb = (ks * 16 + bco) * 2;
            uint32_t ah[2][4], bb[2][4], bl[2][4];
#pragma unroll
            for (int mi = 0; mi < 2; ++mi)
                ldsm_x4(ah[mi], bAh + (arow + mi * 16) * 80 + kof);
#pragma unroll
            for (int g = 0; g < 2; ++g) {
                ldsm_x4(bb[g], bBh + (brow + g * 16) * 80 + kofb);
                ldsm_x4(bl[g], bBl + (brow + g * 16) * 80 + kofb);
            }
#pragma unroll
            for (int mi = 0; mi < 2; ++mi)
#pragma unroll
                for (int ni = 0; ni < 4; ++ni)
                    mma16816(acc[mi][ni], ah[mi],
                             bb[ni >> 1][(ni & 1) * 2], bb[ni >> 1][(ni & 1) * 2 + 1]);
#pragma unroll
            for (int mi = 0; mi < 2; ++mi)
#pragma unroll
                for (int ni = 0; ni < 4; ++ni)
                    mma16816(acc[mi][ni], ah[mi],
                             bl[ni >> 1][(ni & 1) * 2], bl[ni >> 1][(ni & 1) * 2 + 1]);
#pragma unroll
            for (int mi = 0; mi < 2; ++mi)
                ldsm_x4(ah[mi], bAl + (arow + mi * 16) * 80 + kof);
#pragma unroll
            for (int mi = 0; mi < 2; ++mi)
#pragma unroll
                for (int ni = 0; ni < 4; ++ni)
                    mma16816(acc[mi][ni], ah[mi],
                             bb[ni >> 1][(ni & 1) * 2], bb[ni >> 1][(ni & 1) * 2 + 1]);
        }
    }

    const float* bp = bias0;
    __nv_bfloat16 *Hh = O0h, *Hl = O0l;
    float scale = 1.f;
    if (MODE == 2) {
        const int third = blockIdx.x >> 4;
        bp = (third == 0) ? bias0 : (third == 1) ? bias1 : bias2;
        Hh = (third == 0) ? O0h : (third == 1) ? O1h : O2h;
        Hl = (third == 0) ? O0l : (third == 1) ? O1l : O2l;
        scale = (third == 0) ? 0.125f * 1.44269504088896341f : 1.f;
    }

#pragma unroll
    for (int mi = 0; mi < 2; ++mi) {
#pragma unroll
        for (int ni = 0; ni < 4; ++ni) {
            int row = m0 + wm * 32 + mi * 16 + (lane >> 2);
            int col = n0 + wn * 32 + ni * 8 + (lane & 3) * 2;
            int cc  = col & 1023;
            float b0 = bp[cc], b1 = bp[cc + 1];
            if (MODE == 0) {
                float2 v0 = { acc[mi][ni][0] + b0, acc[mi][ni][1] + b1 };
                float2 v1 = { acc[mi][ni][2] + b0, acc[mi][ni][3] + b1 };
                *(float2*)(Cf + (size_t)row * Dq + cc)       = v0;
                *(float2*)(Cf + (size_t)(row + 8) * Dq + cc) = v1;
            } else {
                float v0 = (acc[mi][ni][0] + b0) * scale;
                float v1 = (acc[mi][ni][1] + b1) * scale;
                float v2 = (acc[mi][ni][2] + b0) * scale;
                float v3 = (acc[mi][ni][3] + b1) * scale;
                __nv_bfloat16 h0 = __float2bfloat16(v0), h1 = __float2bfloat16(v1);
                __nv_bfloat16 h2 = __float2bfloat16(v2), h3 = __float2bfloat16(v3);
                *(__nv_bfloat162*)(Hh + (size_t)row * Dq + cc)       = __halves2bfloat162(h0, h1);
                *(__nv_bfloat162*)(Hh + (size_t)(row + 8) * Dq + cc) = __halves2bfloat162(h2, h3);
                *(__nv_bfloat162*)(Hl + (size_t)row * Dq + cc) =
                    __halves2bfloat162(__float2bfloat16(v0 - __bfloat162float(h0)),
                                       __float2bfloat16(v1 - __bfloat162float(h1)));
                *(__nv_bfloat162*)(Hl + (size_t)(row + 8) * Dq + cc) =
                    __halves2bfloat162(__float2bfloat16(v2 - __bfloat162float(h2)),
                                       __float2bfloat16(v3 - __bfloat162float(h3)));
            }
        }
    }
}

// ---------------------------------------------------------------------------
// Tensor-core flash attention (causal):
//  - Ql kept in persistent SMEM (frees 16 regs -> below spill clamp)
//  - K and V in separate cp.async groups: V load overlaps QK compute
//  - exact fully-masked-warp skip via 'active' predicate (barriers uniform)
// smem: Qh 18KB | Ql 18KB | 2 x (Kh|Kl|Vh|Vl 36KB) = 108KB
// ---------------------------------------------------------------------------
#define ATT_SMEM (2 * 18432 + 2 * 36864)

__global__ void __launch_bounds__(256, 2)
attn_mma(const __nv_bfloat16* __restrict__ Qh_g, const __nv_bfloat16* __restrict__ Ql_g,
         const __nv_bfloat16* __restrict__ Kh_g, const __nv_bfloat16* __restrict__ Kl_g,
         const __nv_bfloat16* __restrict__ Vh_g, const __nv_bfloat16* __restrict__ Vl_g,
         __nv_bfloat16* __restrict__ AOh_g, __nv_bfloat16* __restrict__ AOl_g)
{
    extern __shared__ char smc[];
    const uint32_t smb = smem_u32(smc);
    const int t = threadIdx.x, lane = t & 31, w = t >> 5;
    const int qt = (int)gridDim.x - 1 - (int)blockIdx.x;   // heavy tiles first
    const int b = blockIdx.y >> 4, h = blockIdx.y & 15;
    const size_t row0 = (size_t)b * Tq + qt * 128;

    const uint32_t SQH = smb;
    const uint32_t SQL = smb + 18432;
    const uint32_t SKV = smb + 36864;     // 2 bufs x (KH|KL|VH|VL, 9216 each)

    // ---- prologue: Qh and Ql persistent in smem
#pragma unroll
    for (int i = 0; i < 4; ++i) {
        int idx = t + i * 256, r = idx >> 3, s = idx & 7;
        size_t g = (row0 + r) * Dq + h * 64 + s * 8;
        cp_async16(SQH + r * 144 + s * 16, Qh_g + g);
        cp_async16(SQL + r * 144 + s * 16, Ql_g + g);
    }
    asm volatile("cp.async.commit_group;" ::: "memory");
    asm volatile("cp.async.wait_group 0;" ::: "memory");
    __syncthreads();

    const uint32_t arow = w * 16 + (lane & 15);
    const uint32_t aco  = (lane >> 4) * 8;

    auto issue_k = [&](int jt) {
        const uint32_t kb = SKV + (uint32_t)(jt & 1) * 36864;
#pragma unroll
        for (int i = 0; i < 4; ++i) {
            int idx = t + i * 256;
            int mat = idx >> 9, rem = idx & 511, r = rem >> 3, s = rem & 7;
            const __nv_bfloat16* src = (mat == 0) ? Kh_g : Kl_g;
            size_t g = ((size_t)b * Tq + jt * 64 + r) * Dq + h * 64 + s * 8;
            cp_async16(kb + mat * 9216 + r * 144 + s * 16, src + g);
        }
        asm volatile("cp.async.commit_group;" ::: "memory");
    };
    auto issue_v = [&](int jt) {
        const uint32_t kb = SKV + (uint32_t)(jt & 1) * 36864 + 18432;
#pragma unroll
        for (int i = 0; i < 4; ++i) {
            int idx = t + i * 256;
            int mat = idx >> 9, rem = idx & 511, r = rem >> 3, s = rem & 7;
            const __nv_bfloat16* src = (mat == 0) ? Vh_g : Vl_g;
            size_t g = ((size_t)b * Tq + jt * 64 + r) * Dq + h * 64 + s * 8;
            cp_async16(kb + mat * 9216 + r * 144 + s * 16, src + g);
        }
        asm volatile("cp.async.commit_group;" ::: "memory");
    };

    float m0 = -1e30f, m1 = -1e30f, l0 = 0.f, l1 = 0.f;
    float oac[8][4];
#pragma unroll
    for (int ng = 0; ng < 8; ++ng)
#pragma unroll
        for (int k = 0; k < 4; ++k) oac[ng][k] = 0.f;

    const uint32_t krow = ((lane >> 4) & 1) * 8 + (lane & 7);
    const uint32_t kco  = ((lane >> 3) & 1) * 8;
    const uint32_t vrow = ((lane >> 3) & 1) * 8 + (lane & 7);
    const uint32_t vco  = ((lane >> 4) & 1) * 8;

    const int jtmax = 2 * qt + 1;
    issue_k(0);
    issue_v(0);

    float sac[8][4];
    float mn0, mn1, a0, a1;

    for (int jt = 0; jt <= jtmax; ++jt) {
        // K(jt) complete (V(jt) may still be in flight)
        asm volatile("cp.async.wait_group 1;" ::: "memory");
        __syncthreads();
        if (jt + 1 <= jtmax) { issue_k(jt + 1); issue_v(jt + 1); }

        const bool active = (jt * 64 <= qt * 128 + w * 16 + 15);
        const uint32_t SKH = SKV + (uint32_t)(jt & 1) * 36864;
        const uint32_t SKL = SKH + 9216, SVH = SKH + 18432, SVL = SKH + 27648;

        if (active) {
            // ---- S = Q @ K^T (3-pass split; Qh/Ql fragments from smem)
#pragma unroll
            for (int ng = 0; ng < 8; ++ng)
#pragma unroll
                for (int k = 0; k < 4; ++k) sac[ng][k] = 0.f;

#pragma unroll
            for (int ks = 0; ks < 4; ++ks) {
                uint32_t qh[4], qlr[4];
                ldsm_x4(qh,  SQH + arow * 144 + (ks * 16 + aco) * 2);
                ldsm_x4(qlr, SQL + arow * 144 + (ks * 16 + aco) * 2);
#pragma unroll
                for (int g = 0; g < 4; ++g) {
                    uint32_t kb[4];
                    ldsm_x4(kb, SKH + (g * 16 + krow) * 144 + (ks * 16 + kco) * 2);
                    mma16816(sac[2*g],   qh,  kb[0], kb[1]);
                    mma16816(sac[2*g+1], qh,  kb[2], kb[3]);
                    mma16816(sac[2*g],   qlr, kb[0], kb[1]);
                    mma16816(sac[2*g+1], qlr, kb[2], kb[3]);
                }
#pragma unroll
                for (int g = 0; g < 4; ++g) {
                    uint32_t kb[4];
                    ldsm_x4(kb, SKL + (g * 16 + krow) * 144 + (ks * 16 + kco) * 2);
                    mma16816(sac[2*g],   qh, kb[0], kb[1]);
                    mma16816(sac[2*g+1], qh, kb[2], kb[3]);
                }
            }

            // ---- causal mask
            if (jt >= 2 * qt) {
                int q0 = qt * 128 + w * 16 + (lane >> 2);
#pragma unroll
                for (int ng = 0; ng < 8; ++ng) {
                    int k0 = jt * 64 + ng * 8 + (lane & 3) * 2;
                    if (k0     > q0)     sac[ng][0] = -1e30f;
                    if (k0 + 1 > q0)     sac[ng][1] = -1e30f;
                    if (k0     > q0 + 8) sac[ng][2] = -1e30f;
                    if (k0 + 1 > q0 + 8) sac[ng][3] = -1e30f;
                }
            }

            // ---- row max + rescale factors
            float mx0 = -1e30f, mx1 = -1e30f;
#pragma unroll
            for (int ng = 0; ng < 8; ++ng) {
                mx0 = fmaxf(mx0, fmaxf(sac[ng][0], sac[ng][1]));
                mx1 = fmaxf(mx1, fmaxf(sac[ng][2], sac[ng][3]));
            }
            mx0 = fmaxf(mx0, __shfl_xor_sync(0xffffffffu, mx0, 1));
            mx0 = fmaxf(mx0, __shfl_xor_sync(0xffffffffu, mx0, 2));
            mx1 = fmaxf(mx1, __shfl_xor_sync(0xffffffffu, mx1, 1));
            mx1 = fmaxf(mx1, __shfl_xor_sync(0xffffffffu, mx1, 2));
            mn0 = fmaxf(m0, mx0); mn1 = fmaxf(m1, mx1);
            a0 = exp2f(m0 - mn0); a1 = exp2f(m1 - mn1);
            m0 = mn0; m1 = mn1;
#pragma unroll
            for (int ng = 0; ng < 8; ++ng) {
                oac[ng][0] *= a0; oac[ng][1] *= a0;
                oac[ng][2] *= a1; oac[ng][3] *= a1;
            }
        }

        // V(jt) complete; make all threads' V copies visible
        if (jt + 1 <= jtmax)
            asm volatile("cp.async.wait_group 2;" ::: "memory");
        else
            asm volatile("cp.async.wait_group 0;" ::: "memory");
        __syncthreads();

        if (active) {
            // ---- interleaved softmax + PV per key-group
            float rs0 = 0.f, rs1 = 0.f;
#pragma unroll
            for (int ks = 0; ks < 4; ++ks) {
                float* p0 = sac[2*ks];
                float* p1 = sac[2*ks+1];
                p0[0] = exp2f(p0[0] - mn0); p0[1] = exp2f(p0[1] - mn0);
                p0[2] = exp2f(p0[2] - mn1); p0[3] = exp2f(p0[3] - mn1);
                p1[0] = exp2f(p1[0] - mn0); p1[1] = exp2f(p1[1] - mn0);
                p1[2] = exp2f(p1[2] - mn1); p1[3] = exp2f(p1[3] - mn1);
                rs0 += p0[0] + p0[1] + p1[0] + p1[1];
                rs1 += p0[2] + p0[3] + p1[2] + p1[3];

                uint32_t ph[4], pl[4];
                ph[0] = pack_bf16x2(p0[0], p0[1]);
                ph[1] = pack_bf16x2(p0[2], p0[3]);
                ph[2] = pack_bf16x2(p1[0], p1[1]);
                ph[3] = pack_bf16x2(p1[2], p1[3]);
                {
                    __nv_bfloat162 t0 = *(__nv_bfloat162*)&ph[0];
                    __nv_bfloat162 t1 = *(__nv_bfloat162*)&ph[1];
                    __nv_bfloat162 t2 = *(__nv_bfloat162*)&ph[2];
                    __nv_bfloat162 t3 = *(__nv_bfloat162*)&ph[3];
                    pl[0] = pack_bf16x2(p0[0] - __bfloat162float(t0.x), p0[1] - __bfloat162float(t0.y));
                    pl[1] = pack_bf16x2(p0[2] - __bfloat162float(t1.x), p0[3] - __bfloat162float(t1.y));
                    pl[2] = pack_bf16x2(p1[0] - __bfloat162float(t2.x), p1[1] - __bfloat162float(t2.y));
                    pl[3] = pack_bf16x2(p1[2] - __bfloat162float(t3.x), p1[3] - __bfloat162float(t3.y));
                }
#pragma unroll
                for (int g = 0; g < 4; ++g) {
                    uint32_t vb[4];
                    ldsm_x4_t(vb, SVH + (ks * 16 + vrow) * 144 + (g * 16 + vco) * 2);
                    mma16816(oac[2*g],   ph, vb[0], vb[1]);
                    mma16816(oac[2*g+1], ph, vb[2], vb[3]);
                    mma16816(oac[2*g],   pl, vb[0], vb[1]);
                    mma16816(oac[2*g+1], pl, vb[2], vb[3]);
                    ldsm_x4_t(vb, SVL + (ks * 16 + vrow) * 144 + (g * 16 + vco) * 2);
                    mma16816(oac[2*g],   ph, vb[0], vb[1]);
                    mma16816(oac[2*g+1], ph, vb[2], vb[3]);
                }
            }

            rs0 += __shfl_xor_sync(0xffffffffu, rs0, 1);
            rs0 += __shfl_xor_sync(0xffffffffu, rs0, 2);
            rs1 += __shfl_xor_sync(0xffffffffu, rs1, 1);
            rs1 += __shfl_xor_sync(0xffffffffu, rs1, 2);
            l0 = l0 * a0 + rs0; l1 = l1 * a1 + rs1;
        }
    }

    float i0 = 1.f / l0, i1 = 1.f / l1;
    size_t gr0 = row0 + w * 16 + (lane >> 2);
#pragma unroll
    for (int ng = 0; ng < 8; ++ng) {
        int col = h * 64 + ng * 8 + (lane & 3) * 2;
        float v0 = oac[ng][0] * i0, v1 = oac[ng][1] * i0;
        float v2 = oac[ng][2] * i1, v3 = oac[ng][3] * i1;
        __nv_bfloat16 h0 = __float2bfloat16(v0), h1 = __float2bfloat16(v1);
        __nv_bfloat16 h2 = __float2bfloat16(v2), h3 = __float2bfloat16(v3);
        *(__nv_bfloat162*)(AOh_g + gr0 * Dq + col)       = __halves2bfloat162(h0, h1);
        *(__nv_bfloat162*)(AOh_g + (gr0 + 8) * Dq + col) = __halves2bfloat162(h2, h3);
        *(__nv_bfloat162*)(AOl_g + gr0 * Dq + col) =
            __halves2bfloat162(__float2bfloat16(v0 - __bfloat162float(h0)),
                               __float2bfloat16(v1 - __bfloat162float(h1)));
        *(__nv_bfloat162*)(AOl_g + (gr0 + 8) * Dq + col) =
            __halves2bfloat162(__float2bfloat16(v2 - __bfloat162float(h2)),
                               __float2bfloat16(v3 - __bfloat162float(h3)));
    }
}

// ---------------------------------------------------------------------------
extern "C" void kernel_launch(void* const* d_in, const int* in_sizes, int n_in,
                              void* d_out, int out_size)
{
    const float* x  = (const float*)d_in[0];
    const float* Wq = (const float*)d_in[2];
    const float* bq = (const float*)d_in[3];
    const float* Wk = (const float*)d_in[4];
    const float* bk = (const float*)d_in[5];
    const float* Wv = (const float*)d_in[6];
    const float* bv = (const float*)d_in[7];
    const float* Wo = (const float*)d_in[8];
    const float* bo = (const float*)d_in[9];
    float* out = (float*)d_out;

    __nv_bfloat16 *ahi, *alo, *whi, *wlo;
    __nv_bfloat16 *qh, *qlp, *kh, *kl, *vh, *vl, *aoh, *aol;
    cudaGetSymbolAddress((void**)&ahi, g_Ahi);
    cudaGetSymbolAddress((void**)&alo, g_Alo);
    cudaGetSymbolAddress((void**)&whi, g_Whi);
    cudaGetSymbolAddress((void**)&wlo, g_Wlo);
    cudaGetSymbolAddress((void**)&qh,  g_Qh);
    cudaGetSymbolAddress((void**)&qlp, g_Ql);
    cudaGetSymbolAddress((void**)&kh,  g_Kh);
    cudaGetSymbolAddress((void**)&kl,  g_Kl);
    cudaGetSymbolAddress((void**)&vh,  g_Vh);
    cudaGetSymbolAddress((void**)&vl,  g_Vl);
    cudaGetSymbolAddress((void**)&aoh, g_AOh);
    cudaGetSymbolAddress((void**)&aol, g_AOl);

    cudaFuncSetAttribute(gemm_mma<0>, cudaFuncAttributeMaxDynamicSharedMemorySize, GEMM_SMEM);
    cudaFuncSetAttribute(gemm_mma<2>, cudaFuncAttributeMaxDynamicSharedMemorySize, GEMM_SMEM);
    cudaFuncSetAttribute(attn_mma, cudaFuncAttributeMaxDynamicSharedMemorySize, ATT_SMEM);

    const int NPROJ = Mq * Dq;

    split_kernel<<<NPROJ / 1024, 256>>>(x, ahi, alo, NPROJ);
    dim3 tsg(32, 32, 4), tsb(32, 8);
    transpose_split4_kernel<<<tsg, tsb>>>(Wq, Wk, Wv, Wo, whi, wlo);

    dim3 qkvgrid(3 * Dq / 64, Mq / 64);    // (48, 64)
    gemm_mma<2><<<qkvgrid, 128, GEMM_SMEM>>>(ahi, alo, whi, wlo,
                                             bq, bk, bv, nullptr,
                                             qh, qlp, kh, kl, vh, vl);

    dim3 agrid(Tq / 128, Bq * Hq);
    attn_mma<<<agrid, 256, ATT_SMEM>>>(qh, qlp, kh, kl, vh, vl, aoh, aol);

    dim3 ogrid(Dq / 64, Mq / 64);          // (16, 64)
    gemm_mma<0><<<ogrid, 128, GEMM_SMEM>>>(aoh, aol, whi + 3 * (size_t)Dq * Dq,
                                           wlo + 3 * (size_t)Dq * Dq,
                                           bo, nullptr, nullptr, out,
                                           nullptr, nullptr, nullptr, nullptr,
                                           nullptr, nullptr);
}

// round 15
// speedup vs baseline: 1.0192x; 1.0192x over previous
#include <cuda_runtime.h>
#include <cuda_bf16.h>
#include <cstdint>
#include <cstddef>

#define Bq   2
#define Tq   2048
#define Dq   1024
#define Hq   16
#define DKq  64
#define Mq   (Bq*Tq)     // 4096

// ---------------- scratch (device globals: allocation-free) ----------------
__device__ __align__(16) __nv_bfloat16 g_Ahi[Mq * Dq];
__device__ __align__(16) __nv_bfloat16 g_Alo[Mq * Dq];
__device__ __align__(16) __nv_bfloat16 g_Whi[4][Dq * Dq];   // transposed [n][k]
__device__ __align__(16) __nv_bfloat16 g_Wlo[4][Dq * Dq];
__device__ __align__(16) __nv_bfloat16 g_Qh[Mq * Dq];
__device__ __align__(16) __nv_bfloat16 g_Ql[Mq * Dq];
__device__ __align__(16) __nv_bfloat16 g_Kh[Mq * Dq];
__device__ __align__(16) __nv_bfloat16 g_Kl[Mq * Dq];
__device__ __align__(16) __nv_bfloat16 g_Vh[Mq * Dq];
__device__ __align__(16) __nv_bfloat16 g_Vl[Mq * Dq];
__device__ __align__(16) __nv_bfloat16 g_AOh[Mq * Dq];
__device__ __align__(16) __nv_bfloat16 g_AOl[Mq * Dq];

// ---------------------------------------------------------------------------
__device__ __forceinline__ uint32_t smem_u32(const void* p) {
    uint32_t a;
    asm("{ .reg .u64 t; cvta.to.shared.u64 t, %1; cvt.u32.u64 %0, t; }" : "=r"(a) : "l"(p));
    return a;
}
__device__ __forceinline__ void cp_async16(uint32_t saddr, const void* gaddr) {
    asm volatile("cp.async.cg.shared.global [%0], [%1], 16;" :: "r"(saddr), "l"(gaddr));
}
__device__ __forceinline__ void ldsm_x4(uint32_t* r, uint32_t saddr) {
    asm volatile("ldmatrix.sync.aligned.m8n8.x4.shared.b16 {%0,%1,%2,%3}, [%4];"
                 : "=r"(r[0]), "=r"(r[1]), "=r"(r[2]), "=r"(r[3]) : "r"(saddr));
}
__device__ __forceinline__ void ldsm_x4_t(uint32_t* r, uint32_t saddr) {
    asm volatile("ldmatrix.sync.aligned.m8n8.x4.trans.shared.b16 {%0,%1,%2,%3}, [%4];"
                 : "=r"(r[0]), "=r"(r[1]), "=r"(r[2]), "=r"(r[3]) : "r"(saddr));
}
__device__ __forceinline__ void mma16816(float* d, const uint32_t* a, uint32_t b0, uint32_t b1) {
    asm volatile(
        "mma.sync.aligned.m16n8k16.row.col.f32.bf16.bf16.f32 "
        "{%0,%1,%2,%3}, {%4,%5,%6,%7}, {%8,%9}, {%0,%1,%2,%3};"
        : "+f"(d[0]), "+f"(d[1]), "+f"(d[2]), "+f"(d[3])
        : "r"(a[0]), "r"(a[1]), "r"(a[2]), "r"(a[3]), "r"(b0), "r"(b1));
}
__device__ __forceinline__ uint32_t pack_bf16x2(float a, float b) {
    __nv_bfloat162 t = __halves2bfloat162(__float2bfloat16(a), __float2bfloat16(b));
    return *(uint32_t*)&t;
}

// ---------------------------------------------------------------------------
__global__ void split_kernel(const float* __restrict__ src,
                             __nv_bfloat16* __restrict__ hi,
                             __nv_bfloat16* __restrict__ lo, int n)
{
    int i = (blockIdx.x * blockDim.x + threadIdx.x) * 4;
    if (i >= n) return;
    float4 v = *(const float4*)(src + i);
    __nv_bfloat16 h0 = __float2bfloat16(v.x), h1 = __float2bfloat16(v.y);
    __nv_bfloat16 h2 = __float2bfloat16(v.z), h3 = __float2bfloat16(v.w);
    __nv_bfloat16 l0 = __float2bfloat16(v.x - __bfloat162float(h0));
    __nv_bfloat16 l1 = __float2bfloat16(v.y - __bfloat162float(h1));
    __nv_bfloat16 l2 = __float2bfloat16(v.z - __bfloat162float(h2));
    __nv_bfloat16 l3 = __float2bfloat16(v.w - __bfloat162float(h3));
    ((__nv_bfloat162*)(hi + i))[0] = __halves2bfloat162(h0, h1);
    ((__nv_bfloat162*)(hi + i))[1] = __halves2bfloat162(h2, h3);
    ((__nv_bfloat162*)(lo + i))[0] = __halves2bfloat162(l0, l1);
    ((__nv_bfloat162*)(lo + i))[1] = __halves2bfloat162(l2, l3);
}

__global__ void transpose_split4_kernel(const float* __restrict__ W0,
                                        const float* __restrict__ W1,
                                        const float* __restrict__ W2,
                                        const float* __restrict__ W3,
                                        __nv_bfloat16* __restrict__ hi,
                                        __nv_bfloat16* __restrict__ lo)
{
    __shared__ float tile[32][33];
    const int wsel = blockIdx.z;
    const float* W = (wsel == 0) ? W0 : (wsel == 1) ? W1 : (wsel == 2) ? W2 : W3;
    __nv_bfloat16* hp = hi + (size_t)wsel * Dq * Dq;
    __nv_bfloat16* lp = lo + (size_t)wsel * Dq * Dq;
    int n0 = blockIdx.x * 32, k0 = blockIdx.y * 32;
    int x = threadIdx.x, y = threadIdx.y;
#pragma unroll
    for (int r = 0; r < 32; r += 8)
        tile[y + r][x] = W[(size_t)(k0 + y + r) * Dq + n0 + x];
    __syncthreads();
#pragma unroll
    for (int r = 0; r < 32; r += 8) {
        float v = tile[x][y + r];
        __nv_bfloat16 h = __float2bfloat16(v);
        hp[(size_t)(n0 + y + r) * Dq + k0 + x] = h;
        lp[(size_t)(n0 + y + r) * Dq + k0 + x] = __float2bfloat16(v - __bfloat162float(h));
    }
}

// ---------------------------------------------------------------------------
// Fused-split GEMM (round-13 config, measured best): CTA 64x64, 4 warps,
// BK=32, 2-stage cp.async, occ 5.
// ---------------------------------------------------------------------------
#define GSTAGE 20480
#define GEMM_SMEM (2 * GSTAGE)

template<int MODE>
__global__ void __launch_bounds__(128, 5)
gemm_mma(const __nv_bfloat16* __restrict__ Ah, const __nv_bfloat16* __restrict__ Al,
         const __nv_bfloat16* __restrict__ Bh, const __nv_bfloat16* __restrict__ Bl,
         const float* __restrict__ bias0, const float* __restrict__ bias1,
         const float* __restrict__ bias2,
         float* __restrict__ Cf,
         __nv_bfloat16* __restrict__ O0h, __nv_bfloat16* __restrict__ O0l,
         __nv_bfloat16* __restrict__ O1h, __nv_bfloat16* __restrict__ O1l,
         __nv_bfloat16* __restrict__ O2h, __nv_bfloat16* __restrict__ O2l)
{
    extern __shared__ char smc[];
    const uint32_t smb = smem_u32(smc);
    const int t = threadIdx.x, lane = t & 31, wid = t >> 5;
    const int wm = wid >> 1, wn = wid & 1;
    const int m0 = blockIdx.y * 64, n0 = blockIdx.x * 64;

    float acc[2][4][4];
#pragma unroll
    for (int i = 0; i < 2; i++)
#pragma unroll
        for (int j = 0; j < 4; j++)
#pragma unroll
            for (int k = 0; k < 4; k++) acc[i][j][k] = 0.f;

    const __nv_bfloat16* Amats[2] = { Ah + (size_t)m0 * Dq, Al + (size_t)m0 * Dq };
    const __nv_bfloat16* Bmats[2] = { Bh + (size_t)n0 * Dq, Bl + (size_t)n0 * Dq };

    auto issue = [&](int c) {
        const uint32_t base = smb + (uint32_t)(c & 1) * GSTAGE;
        const int kk = c * 32;
#pragma unroll
        for (int m = 0; m < 2; ++m) {
            const __nv_bfloat16* s = Amats[m] + kk;
#pragma unroll
            for (int it = 0; it < 2; ++it) {
                int idx = t + it * 128;
                int r = idx >> 2, seg = idx & 3;
                cp_async16(base + m * 5120 + r * 80 + seg * 16,
                           s + (size_t)r * Dq + seg * 8);
            }
        }
#pragma unroll
        for (int m = 0; m < 2; ++m) {
            const __nv_bfloat16* s = Bmats[m] + kk;
#pragma unroll
            for (int it = 0; it < 2; ++it) {
                int idx = t + it * 128;
                int r = idx >> 2, seg = idx & 3;
                cp_async16(base + 10240 + m * 5120 + r * 80 + seg * 16,
                           s + (size_t)r * Dq + seg * 8);
            }
        }
        asm volatile("cp.async.commit_group;" ::: "memory");
    };

    issue(0);

    const int arow = wm * 32 + (lane & 15);
    const int aco  = (lane >> 4) * 8;
    const int brow = wn * 32 + ((lane >> 4) & 1) * 8 + (lane & 7);
    const int bco  = ((lane >> 3) & 1) * 8;

    for (int c = 0; c < 32; ++c) {
        asm volatile("cp.async.wait_group 0;" ::: "memory");
        __syncthreads();
        if (c + 1 < 32) issue(c + 1);

        const uint32_t bAh = smb + (uint32_t)(c & 1) * GSTAGE;
        const uint32_t bAl = bAh + 5120, bBh = bAh + 10240, bBl = bAh + 15360;

#pragma unroll
        for (int ks = 0; ks < 2; ++ks) {
            const int kof  = (ks * 16 + aco) * 2;
            const int kofb = (ks * 16 + bco) * 2;
            uint32_t ah[2][4], bb[2][4], bl[2][4];
#pragma unroll
            for (int mi = 0; mi < 2; ++mi)
                ldsm_x4(ah[mi], bAh + (arow + mi * 16) * 80 + kof);
#pragma unroll
            for (int g = 0; g < 2; ++g) {
                ldsm_x4(bb[g], bBh + (brow + g * 16) * 80 + kofb);
                ldsm_x4(bl[g], bBl + (brow + g * 16) * 80 + kofb);
            }
#pragma unroll
            for (int mi = 0; mi < 2; ++mi)
#pragma unroll
                for (int ni = 0; ni < 4; ++ni)
                    mma16816(acc[mi][ni], ah[mi],
                             bb[ni >> 1][(ni & 1) * 2], bb[ni >> 1][(ni & 1) * 2 + 1]);
#pragma unroll
            for (int mi = 0; mi < 2; ++mi)
#pragma unroll
                for (int ni = 0; ni < 4; ++ni)
                    mma16816(acc[mi][ni], ah[mi],
                             bl[ni >> 1][(ni & 1) * 2], bl[ni >> 1][(ni & 1) * 2 + 1]);
#pragma unroll
            for (int mi = 0; mi < 2; ++mi)
                ldsm_x4(ah[mi], bAl + (arow + mi * 16) * 80 + kof);
#pragma unroll
            for (int mi = 0; mi < 2; ++mi)
#pragma unroll
                for (int ni = 0; ni < 4; ++ni)
                    mma16816(acc[mi][ni], ah[mi],
                             bb[ni >> 1][(ni & 1) * 2], bb[ni >> 1][(ni & 1) * 2 + 1]);
        }
    }

    const float* bp = bias0;
    __nv_bfloat16 *Hh = O0h, *Hl = O0l;
    float scale = 1.f;
    if (MODE == 2) {
        const int third = blockIdx.x >> 4;
        bp = (third == 0) ? bias0 : (third == 1) ? bias1 : bias2;
        Hh = (third == 0) ? O0h : (third == 1) ? O1h : O2h;
        Hl = (third == 0) ? O0l : (third == 1) ? O1l : O2l;
        scale = (third == 0) ? 0.125f * 1.44269504088896341f : 1.f;
    }

#pragma unroll
    for (int mi = 0; mi < 2; ++mi) {
#pragma unroll
        for (int ni = 0; ni < 4; ++ni) {
            int row = m0 + wm * 32 + mi * 16 + (lane >> 2);
            int col = n0 + wn * 32 + ni * 8 + (lane & 3) * 2;
            int cc  = col & 1023;
            float b0 = bp[cc], b1 = bp[cc + 1];
            if (MODE == 0) {
                float2 v0 = { acc[mi][ni][0] + b0, acc[mi][ni][1] + b1 };
                float2 v1 = { acc[mi][ni][2] + b0, acc[mi][ni][3] + b1 };
                *(float2*)(Cf + (size_t)row * Dq + cc)       = v0;
                *(float2*)(Cf + (size_t)(row + 8) * Dq + cc) = v1;
            } else {
                float v0 = (acc[mi][ni][0] + b0) * scale;
                float v1 = (acc[mi][ni][1] + b1) * scale;
                float v2 = (acc[mi][ni][2] + b0) * scale;
                float v3 = (acc[mi][ni][3] + b1) * scale;
                __nv_bfloat16 h0 = __float2bfloat16(v0), h1 = __float2bfloat16(v1);
                __nv_bfloat16 h2 = __float2bfloat16(v2), h3 = __float2bfloat16(v3);
                *(__nv_bfloat162*)(Hh + (size_t)row * Dq + cc)       = __halves2bfloat162(h0, h1);
                *(__nv_bfloat162*)(Hh + (size_t)(row + 8) * Dq + cc) = __halves2bfloat162(h2, h3);
                *(__nv_bfloat162*)(Hl + (size_t)row * Dq + cc) =
                    __halves2bfloat162(__float2bfloat16(v0 - __bfloat162float(h0)),
                                       __float2bfloat16(v1 - __bfloat162float(h1)));
                *(__nv_bfloat162*)(Hl + (size_t)(row + 8) * Dq + cc) =
                    __halves2bfloat162(__float2bfloat16(v2 - __bfloat162float(h2)),
                                       __float2bfloat16(v3 - __bfloat162float(h3)));
            }
        }
    }
}

// ---------------------------------------------------------------------------
// Tensor-core flash attention (causal), R13 base + paired key-groups:
// B-fragments loaded for g-pairs so 4 accumulator chains interleave per block.
// ---------------------------------------------------------------------------
#define ATT_SMEM (18432 + 2 * 36864)

__global__ void __launch_bounds__(256, 2)
attn_mma(const __nv_bfloat16* __restrict__ Qh_g, const __nv_bfloat16* __restrict__ Ql_g,
         const __nv_bfloat16* __restrict__ Kh_g, const __nv_bfloat16* __restrict__ Kl_g,
         const __nv_bfloat16* __restrict__ Vh_g, const __nv_bfloat16* __restrict__ Vl_g,
         __nv_bfloat16* __restrict__ AOh_g, __nv_bfloat16* __restrict__ AOl_g)
{
    extern __shared__ char smc[];
    const uint32_t smb = smem_u32(smc);
    const int t = threadIdx.x, lane = t & 31, w = t >> 5;
    const int qt = (int)gridDim.x - 1 - (int)blockIdx.x;   // heavy tiles first
    const int b = blockIdx.y >> 4, h = blockIdx.y & 15;
    const size_t row0 = (size_t)b * Tq + qt * 128;

    const uint32_t SQH = smb;
    const uint32_t SKV = smb + 18432;

#pragma unroll
    for (int i = 0; i < 4; ++i) {
        int idx = t + i * 256, r = idx >> 3, s = idx & 7;
        size_t g = (row0 + r) * Dq + h * 64 + s * 8;
        cp_async16(SQH + r * 144 + s * 16, Qh_g + g);
        cp_async16(SKV + r * 144 + s * 16, Ql_g + g);
    }
    asm volatile("cp.async.commit_group;" ::: "memory");
    asm volatile("cp.async.wait_group 0;" ::: "memory");
    __syncthreads();

    const uint32_t arow = w * 16 + (lane & 15);
    const uint32_t aco  = (lane >> 4) * 8;
    uint32_t ql[4][4];
#pragma unroll
    for (int ks = 0; ks < 4; ++ks)
        ldsm_x4(ql[ks], SKV + arow * 144 + (ks * 16 + aco) * 2);
    __syncthreads();

    auto issue_kv = [&](int jt) {
        const uint32_t kb = SKV + (uint32_t)(jt & 1) * 36864;
#pragma unroll
        for (int i = 0; i < 8; ++i) {
            int idx = t + i * 256;
            int mat = idx >> 9, rem = idx & 511, r = rem >> 3, s = rem & 7;
            const __nv_bfloat16* src = (mat == 0) ? Kh_g : (mat == 1) ? Kl_g
                                     : (mat == 2) ? Vh_g : Vl_g;
            size_t g = ((size_t)b * Tq + jt * 64 + r) * Dq + h * 64 + s * 8;
            cp_async16(kb + mat * 9216 + r * 144 + s * 16, src + g);
        }
        asm volatile("cp.async.commit_group;" ::: "memory");
    };

    float m0 = -1e30f, m1 = -1e30f, l0 = 0.f, l1 = 0.f;
    float oac[8][4];
#pragma unroll
    for (int ng = 0; ng < 8; ++ng)
#pragma unroll
        for (int k = 0; k < 4; ++k) oac[ng][k] = 0.f;

    const uint32_t krow = ((lane >> 4) & 1) * 8 + (lane & 7);
    const uint32_t kco  = ((lane >> 3) & 1) * 8;
    const uint32_t vrow = ((lane >> 3) & 1) * 8 + (lane & 7);
    const uint32_t vco  = ((lane >> 4) & 1) * 8;

    const int jtmax = 2 * qt + 1;
    issue_kv(0);

    for (int jt = 0; jt <= jtmax; ++jt) {
        asm volatile("cp.async.wait_group 0;" ::: "memory");
        __syncthreads();
        if (jt + 1 <= jtmax) issue_kv(jt + 1);

        // exact skip: tile fully above this warp's q rows -> masked no-op
        if (jt * 64 > qt * 128 + w * 16 + 15) continue;

        const uint32_t SKH = SKV + (uint32_t)(jt & 1) * 36864;
        const uint32_t SKL = SKH + 9216, SVH = SKH + 18432, SVL = SKH + 27648;

        // ---- S = Q @ K^T (3-pass split), key-groups in pairs -> 4 chains
        float sac[8][4];
#pragma unroll
        for (int ng = 0; ng < 8; ++ng)
#pragma unroll
            for (int k = 0; k < 4; ++k) sac[ng][k] = 0.f;

#pragma unroll
        for (int ks = 0; ks < 4; ++ks) {
            uint32_t qh[4];
            ldsm_x4(qh, SQH + arow * 144 + (ks * 16 + aco) * 2);
#pragma unroll
            for (int gp = 0; gp < 2; ++gp) {
                const int g0 = gp * 2, g1 = g0 + 1;
                uint32_t k0r[4], k1r[4];
                ldsm_x4(k0r, SKH + (g0 * 16 + krow) * 144 + (ks * 16 + kco) * 2);
                ldsm_x4(k1r, SKH + (g1 * 16 + krow) * 144 + (ks * 16 + kco) * 2);
                // interleave 4 accumulator chains
                mma16816(sac[2*g0],   qh,     k0r[0], k0r[1]);
                mma16816(sac[2*g0+1], qh,     k0r[2], k0r[3]);
                mma16816(sac[2*g1],   qh,     k1r[0], k1r[1]);
                mma16816(sac[2*g1+1], qh,     k1r[2], k1r[3]);
                mma16816(sac[2*g0],   ql[ks], k0r[0], k0r[1]);
                mma16816(sac[2*g0+1], ql[ks], k0r[2], k0r[3]);
                mma16816(sac[2*g1],   ql[ks], k1r[0], k1r[1]);
                mma16816(sac[2*g1+1], ql[ks], k1r[2], k1r[3]);
                // K-lo pass for same pair (reuse regs)
                ldsm_x4(k0r, SKL + (g0 * 16 + krow) * 144 + (ks * 16 + kco) * 2);
                ldsm_x4(k1r, SKL + (g1 * 16 + krow) * 144 + (ks * 16 + kco) * 2);
                mma16816(sac[2*g0],   qh, k0r[0], k0r[1]);
                mma16816(sac[2*g0+1], qh, k0r[2], k0r[3]);
                mma16816(sac[2*g1],   qh, k1r[0], k1r[1]);
                mma16816(sac[2*g1+1], qh, k1r[2], k1r[3]);
            }
        }

        // ---- causal mask
        if (jt >= 2 * qt) {
            int q0 = qt * 128 + w * 16 + (lane >> 2);
#pragma unroll
            for (int ng = 0; ng < 8; ++ng) {
                int k0 = jt * 64 + ng * 8 + (lane & 3) * 2;
                if (k0     > q0)     sac[ng][0] = -1e30f;
                if (k0 + 1 > q0)     sac[ng][1] = -1e30f;
                if (k0     > q0 + 8) sac[ng][2] = -1e30f;
                if (k0 + 1 > q0 + 8) sac[ng][3] = -1e30f;
            }
        }

        // ---- row max + rescale
        float mx0 = -1e30f, mx1 = -1e30f;
#pragma unroll
        for (int ng = 0; ng < 8; ++ng) {
            mx0 = fmaxf(mx0, fmaxf(sac[ng][0], sac[ng][1]));
            mx1 = fmaxf(mx1, fmaxf(sac[ng][2], sac[ng][3]));
        }
        mx0 = fmaxf(mx0, __shfl_xor_sync(0xffffffffu, mx0, 1));
        mx0 = fmaxf(mx0, __shfl_xor_sync(0xffffffffu, mx0, 2));
        mx1 = fmaxf(mx1, __shfl_xor_sync(0xffffffffu, mx1, 1));
        mx1 = fmaxf(mx1, __shfl_xor_sync(0xffffffffu, mx1, 2));
        float mn0 = fmaxf(m0, mx0), mn1 = fmaxf(m1, mx1);
        float a0 = exp2f(m0 - mn0), a1 = exp2f(m1 - mn1);
        m0 = mn0; m1 = mn1;
#pragma unroll
        for (int ng = 0; ng < 8; ++ng) {
            oac[ng][0] *= a0; oac[ng][1] *= a0;
            oac[ng][2] *= a1; oac[ng][3] *= a1;
        }

        // ---- interleaved softmax + PV per key-group; V-groups paired -> 4 chains
        float rs0 = 0.f, rs1 = 0.f;
#pragma unroll
        for (int ks = 0; ks < 4; ++ks) {
            float* p0 = sac[2*ks];
            float* p1 = sac[2*ks+1];
            p0[0] = exp2f(p0[0] - mn0); p0[1] = exp2f(p0[1] - mn0);
            p0[2] = exp2f(p0[2] - mn1); p0[3] = exp2f(p0[3] - mn1);
            p1[0] = exp2f(p1[0] - mn0); p1[1] = exp2f(p1[1] - mn0);
            p1[2] = exp2f(p1[2] - mn1); p1[3] = exp2f(p1[3] - mn1);
            rs0 += p0[0] + p0[1] + p1[0] + p1[1];
            rs1 += p0[2] + p0[3] + p1[2] + p1[3];

            uint32_t ph[4], pl[4];
            ph[0] = pack_bf16x2(p0[0], p0[1]);
            ph[1] = pack_bf16x2(p0[2], p0[3]);
            ph[2] = pack_bf16x2(p1[0], p1[1]);
            ph[3] = pack_bf16x2(p1[2], p1[3]);
            {
                __nv_bfloat162 t0 = *(__nv_bfloat162*)&ph[0];
                __nv_bfloat162 t1 = *(__nv_bfloat162*)&ph[1];
                __nv_bfloat162 t2 = *(__nv_bfloat162*)&ph[2];
                __nv_bfloat162 t3 = *(__nv_bfloat162*)&ph[3];
                pl[0] = pack_bf16x2(p0[0] - __bfloat162float(t0.x), p0[1] - __bfloat162float(t0.y));
                pl[1] = pack_bf16x2(p0[2] - __bfloat162float(t1.x), p0[3] - __bfloat162float(t1.y));
                pl[2] = pack_bf16x2(p1[0] - __bfloat162float(t2.x), p1[1] - __bfloat162float(t2.y));
                pl[3] = pack_bf16x2(p1[2] - __bfloat162float(t3.x), p1[3] - __bfloat162float(t3.y));
            }
#pragma unroll
            for (int gp = 0; gp < 2; ++gp) {
                const int g0 = gp * 2, g1 = g0 + 1;
                uint32_t v0r[4], v1r[4];
                ldsm_x4_t(v0r, SVH + (ks * 16 + vrow) * 144 + (g0 * 16 + vco) * 2);
                ldsm_x4_t(v1r, SVH + (ks * 16 + vrow) * 144 + (g1 * 16 + vco) * 2);
                mma16816(oac[2*g0],   ph, v0r[0], v0r[1]);
                mma16816(oac[2*g0+1], ph, v0r[2], v0r[3]);
                mma16816(oac[2*g1],   ph, v1r[0], v1r[1]);
                mma16816(oac[2*g1+1], ph, v1r[2], v1r[3]);
                mma16816(oac[2*g0],   pl, v0r[0], v0r[1]);
                mma16816(oac[2*g0+1], pl, v0r[2], v0r[3]);
                mma16816(oac[2*g1],   pl, v1r[0], v1r[1]);
                mma16816(oac[2*g1+1], pl, v1r[2], v1r[3]);
                ldsm_x4_t(v0r, SVL + (ks * 16 + vrow) * 144 + (g0 * 16 + vco) * 2);
                ldsm_x4_t(v1r, SVL + (ks * 16 + vrow) * 144 + (g1 * 16 + vco) * 2);
                mma16816(oac[2*g0],   ph, v0r[0], v0r[1]);
                mma16816(oac[2*g0+1], ph, v0r[2], v0r[3]);
                mma16816(oac[2*g1],   ph, v1r[0], v1r[1]);
                mma16816(oac[2*g1+1], ph, v1r[2], v1r[3]);
            }
        }

        rs0 += __shfl_xor_sync(0xffffffffu, rs0, 1);
        rs0 += __shfl_xor_sync(0xffffffffu, rs0, 2);
        rs1 += __shfl_xor_sync(0xffffffffu, rs1, 1);
        rs1 += __shfl_xor_sync(0xffffffffu, rs1, 2);
        l0 = l0 * a0 + rs0; l1 = l1 * a1 + rs1;
    }

    float i0 = 1.f / l0, i1 = 1.f / l1;
    size_t gr0 = row0 + w * 16 + (lane >> 2);
#pragma unroll
    for (int ng = 0; ng < 8; ++ng) {
        int col = h * 64 + ng * 8 + (lane & 3) * 2;
        float v0 = oac[ng][0] * i0, v1 = oac[ng][1] * i0;
        float v2 = oac[ng][2] * i1, v3 = oac[ng][3] * i1;
        __nv_bfloat16 h0 = __float2bfloat16(v0), h1 = __float2bfloat16(v1);
        __nv_bfloat16 h2 = __float2bfloat16(v2), h3 = __float2bfloat16(v3);
        *(__nv_bfloat162*)(AOh_g + gr0 * Dq + col)       = __halves2bfloat162(h0, h1);
        *(__nv_bfloat162*)(AOh_g + (gr0 + 8) * Dq + col) = __halves2bfloat162(h2, h3);
        *(__nv_bfloat162*)(AOl_g + gr0 * Dq + col) =
            __halves2bfloat162(__float2bfloat16(v0 - __bfloat162float(h0)),
                               __float2bfloat16(v1 - __bfloat162float(h1)));
        *(__nv_bfloat162*)(AOl_g + (gr0 + 8) * Dq + col) =
            __halves2bfloat162(__float2bfloat16(v2 - __bfloat162float(h2)),
                               __float2bfloat16(v3 - __bfloat162float(h3)));
    }
}

// ---------------------------------------------------------------------------
extern "C" void kernel_launch(void* const* d_in, const int* in_sizes, int n_in,
                              void* d_out, int out_size)
{
    const float* x  = (const float*)d_in[0];
    const float* Wq = (const float*)d_in[2];
    const float* bq = (const float*)d_in[3];
    const float* Wk = (const float*)d_in[4];
    const float* bk = (const float*)d_in[5];
    const float* Wv = (const float*)d_in[6];
    const float* bv = (const float*)d_in[7];
    const float* Wo = (const float*)d_in[8];
    const float* bo = (const float*)d_in[9];
    float* out = (float*)d_out;

    __nv_bfloat16 *ahi, *alo, *whi, *wlo;
    __nv_bfloat16 *qh, *qlp, *kh, *kl, *vh, *vl, *aoh, *aol;
    cudaGetSymbolAddress((void**)&ahi, g_Ahi);
    cudaGetSymbolAddress((void**)&alo, g_Alo);
    cudaGetSymbolAddress((void**)&whi, g_Whi);
    cudaGetSymbolAddress((void**)&wlo, g_Wlo);
    cudaGetSymbolAddress((void**)&qh,  g_Qh);
    cudaGetSymbolAddress((void**)&qlp, g_Ql);
    cudaGetSymbolAddress((void**)&kh,  g_Kh);
    cudaGetSymbolAddress((void**)&kl,  g_Kl);
    cudaGetSymbolAddress((void**)&vh,  g_Vh);
    cudaGetSymbolAddress((void**)&vl,  g_Vl);
    cudaGetSymbolAddress((void**)&aoh, g_AOh);
    cudaGetSymbolAddress((void**)&aol, g_AOl);

    cudaFuncSetAttribute(gemm_mma<0>, cudaFuncAttributeMaxDynamicSharedMemorySize, GEMM_SMEM);
    cudaFuncSetAttribute(gemm_mma<2>, cudaFuncAttributeMaxDynamicSharedMemorySize, GEMM_SMEM);
    cudaFuncSetAttribute(attn_mma, cudaFuncAttributeMaxDynamicSharedMemorySize, ATT_SMEM);

    const int NPROJ = Mq * Dq;

    split_kernel<<<NPROJ / 1024, 256>>>(x, ahi, alo, NPROJ);
    dim3 tsg(32, 32, 4), tsb(32, 8);
    transpose_split4_kernel<<<tsg, tsb>>>(Wq, Wk, Wv, Wo, whi, wlo);

    dim3 qkvgrid(3 * Dq / 64, Mq / 64);    // (48, 64)
    gemm_mma<2><<<qkvgrid, 128, GEMM_SMEM>>>(ahi, alo, whi, wlo,
                                             bq, bk, bv, nullptr,
                                             qh, qlp, kh, kl, vh, vl);

    dim3 agrid(Tq / 128, Bq * Hq);
    attn_mma<<<agrid, 256, ATT_SMEM>>>(qh, qlp, kh, kl, vh, vl, aoh, aol);

    dim3 ogrid(Dq / 64, Mq / 64);          // (16, 64)
    gemm_mma<0><<<ogrid, 128, GEMM_SMEM>>>(aoh, aol, whi + 3 * (size_t)Dq * Dq,
                                           wlo + 3 * (size_t)Dq * Dq,
                                           bo, nullptr, nullptr, out,
                                           nullptr, nullptr, nullptr, nullptr,
                                           nullptr, nullptr);
}

// round 16
// speedup vs baseline: 1.4398x; 1.4126x over previous
#include <cuda_runtime.h>
#include <cuda_fp16.h>
#include <cstdint>
#include <cstddef>

#define Bq   2
#define Tq   2048
#define Dq   1024
#define Hq   16
#define DKq  64
#define Mq   (Bq*Tq)     // 4096

// ---------------- scratch (device globals: allocation-free) ----------------
__device__ __align__(16) __half g_Ahi[Mq * Dq];
__device__ __align__(16) __half g_Alo[Mq * Dq];
__device__ __align__(16) __half g_W[4][Dq * Dq];     // transposed [n][k], single fp16
__device__ __align__(16) __half g_Qh[Mq * Dq];
__device__ __align__(16) __half g_Ql[Mq * Dq];
__device__ __align__(16) __half g_K[Mq * Dq];
__device__ __align__(16) __half g_V[Mq * Dq];
__device__ __align__(16) __half g_AOh[Mq * Dq];
__device__ __align__(16) __half g_AOl[Mq * Dq];

// ---------------------------------------------------------------------------
__device__ __forceinline__ uint32_t smem_u32(const void* p) {
    uint32_t a;
    asm("{ .reg .u64 t; cvta.to.shared.u64 t, %1; cvt.u32.u64 %0, t; }" : "=r"(a) : "l"(p));
    return a;
}
__device__ __forceinline__ void cp_async16(uint32_t saddr, const void* gaddr) {
    asm volatile("cp.async.cg.shared.global [%0], [%1], 16;" :: "r"(saddr), "l"(gaddr));
}
__device__ __forceinline__ void ldsm_x4(uint32_t* r, uint32_t saddr) {
    asm volatile("ldmatrix.sync.aligned.m8n8.x4.shared.b16 {%0,%1,%2,%3}, [%4];"
                 : "=r"(r[0]), "=r"(r[1]), "=r"(r[2]), "=r"(r[3]) : "r"(saddr));
}
__device__ __forceinline__ void ldsm_x4_t(uint32_t* r, uint32_t saddr) {
    asm volatile("ldmatrix.sync.aligned.m8n8.x4.trans.shared.b16 {%0,%1,%2,%3}, [%4];"
                 : "=r"(r[0]), "=r"(r[1]), "=r"(r[2]), "=r"(r[3]) : "r"(saddr));
}
__device__ __forceinline__ void mma16816(float* d, const uint32_t* a, uint32_t b0, uint32_t b1) {
    asm volatile(
        "mma.sync.aligned.m16n8k16.row.col.f32.f16.f16.f32 "
        "{%0,%1,%2,%3}, {%4,%5,%6,%7}, {%8,%9}, {%0,%1,%2,%3};"
        : "+f"(d[0]), "+f"(d[1]), "+f"(d[2]), "+f"(d[3])
        : "r"(a[0]), "r"(a[1]), "r"(a[2]), "r"(a[3]), "r"(b0), "r"(b1));
}
__device__ __forceinline__ uint32_t pack_h2(float a, float b) {
    __half2 t = __halves2half2(__float2half(a), __float2half(b));
    return *(uint32_t*)&t;
}

// ---------------------------------------------------------------------------
// fp32 -> fp16 hi/lo split
__global__ void split_kernel(const float* __restrict__ src,
                             __half* __restrict__ hi,
                             __half* __restrict__ lo, int n)
{
    int i = (blockIdx.x * blockDim.x + threadIdx.x) * 4;
    if (i >= n) return;
    float4 v = *(const float4*)(src + i);
    __half h0 = __float2half(v.x), h1 = __float2half(v.y);
    __half h2 = __float2half(v.z), h3 = __float2half(v.w);
    __half l0 = __float2half(v.x - __half2float(h0));
    __half l1 = __float2half(v.y - __half2float(h1));
    __half l2 = __float2half(v.z - __half2float(h2));
    __half l3 = __float2half(v.w - __half2float(h3));
    ((__half2*)(hi + i))[0] = __halves2half2(h0, h1);
    ((__half2*)(hi + i))[1] = __halves2half2(h2, h3);
    ((__half2*)(lo + i))[0] = __halves2half2(l0, l1);
    ((__half2*)(lo + i))[1] = __halves2half2(l2, l3);
}

// all 4 weights -> transposed single fp16
__global__ void transpose4_kernel(const float* __restrict__ W0,
                                  const float* __restrict__ W1,
                                  const float* __restrict__ W2,
                                  const float* __restrict__ W3,
                                  __half* __restrict__ dst)
{
    __shared__ float tile[32][33];
    const int wsel = blockIdx.z;
    const float* W = (wsel == 0) ? W0 : (wsel == 1) ? W1 : (wsel == 2) ? W2 : W3;
    __half* hp = dst + (size_t)wsel * Dq * Dq;
    int n0 = blockIdx.x * 32, k0 = blockIdx.y * 32;
    int x = threadIdx.x, y = threadIdx.y;
#pragma unroll
    for (int r = 0; r < 32; r += 8)
        tile[y + r][x] = W[(size_t)(k0 + y + r) * Dq + n0 + x];
    __syncthreads();
#pragma unroll
    for (int r = 0; r < 32; r += 8)
        hp[(size_t)(n0 + y + r) * Dq + k0 + x] = __float2half(tile[x][y + r]);
}

// ---------------------------------------------------------------------------
// fp16 2-pass GEMM: C = (Ah + Al) @ B^T (+bias).  B single fp16.
// CTA 64x64, 4 warps (32x32 warp tile), BK=32, 2-stage cp.async, occ 5.
// Stage: Ah|Al|B = 3 x 5120 = 15360B.
// MODE 0: fp32 out (Wo).  MODE 2: merged QKV; Q->fp16 hi/lo scaled, K/V->fp16.
// ---------------------------------------------------------------------------
#define GSTAGE 15360
#define GEMM_SMEM (2 * GSTAGE)

template<int MODE>
__global__ void __launch_bounds__(128, 5)
gemm_mma(const __half* __restrict__ Ah, const __half* __restrict__ Al,
         const __half* __restrict__ B,
         const float* __restrict__ bias0, const float* __restrict__ bias1,
         const float* __restrict__ bias2,
         float* __restrict__ Cf,
         __half* __restrict__ Oqh, __half* __restrict__ Oql,
         __half* __restrict__ Ok,  __half* __restrict__ Ov)
{
    extern __shared__ char smc[];
    const uint32_t smb = smem_u32(smc);
    const int t = threadIdx.x, lane = t & 31, wid = t >> 5;
    const int wm = wid >> 1, wn = wid & 1;
    const int m0 = blockIdx.y * 64, n0 = blockIdx.x * 64;

    float acc[2][4][4];
#pragma unroll
    for (int i = 0; i < 2; i++)
#pragma unroll
        for (int j = 0; j < 4; j++)
#pragma unroll
            for (int k = 0; k < 4; k++) acc[i][j][k] = 0.f;

    const __half* Amats[2] = { Ah + (size_t)m0 * Dq, Al + (size_t)m0 * Dq };
    const __half* Bmat = B + (size_t)n0 * Dq;

    auto issue = [&](int c) {
        const uint32_t base = smb + (uint32_t)(c & 1) * GSTAGE;
        const int kk = c * 32;
#pragma unroll
        for (int m = 0; m < 2; ++m) {
            const __half* s = Amats[m] + kk;
#pragma unroll
            for (int it = 0; it < 2; ++it) {
                int idx = t + it * 128;
                int r = idx >> 2, seg = idx & 3;
                cp_async16(base + m * 5120 + r * 80 + seg * 16,
                           s + (size_t)r * Dq + seg * 8);
            }
        }
        {
            const __half* s = Bmat + kk;
#pragma unroll
            for (int it = 0; it < 2; ++it) {
                int idx = t + it * 128;
                int r = idx >> 2, seg = idx & 3;
                cp_async16(base + 10240 + r * 80 + seg * 16,
                           s + (size_t)r * Dq + seg * 8);
            }
        }
        asm volatile("cp.async.commit_group;" ::: "memory");
    };

    issue(0);

    const int arow = wm * 32 + (lane & 15);
    const int aco  = (lane >> 4) * 8;
    const int brow = wn * 32 + ((lane >> 4) & 1) * 8 + (lane & 7);
    const int bco  = ((lane >> 3) & 1) * 8;

    for (int c = 0; c < 32; ++c) {
        asm volatile("cp.async.wait_group 0;" ::: "memory");
        __syncthreads();
        if (c + 1 < 32) issue(c + 1);

        const uint32_t bAh = smb + (uint32_t)(c & 1) * GSTAGE;
        const uint32_t bAl = bAh + 5120, bB = bAh + 10240;

#pragma unroll
        for (int ks = 0; ks < 2; ++ks) {
            const int kof  = (ks * 16 + aco) * 2;
            const int kofb = (ks * 16 + bco) * 2;
            uint32_t ah[2][4], bb[2][4];
#pragma unroll
            for (int mi = 0; mi < 2; ++mi)
                ldsm_x4(ah[mi], bAh + (arow + mi * 16) * 80 + kof);
#pragma unroll
            for (int g = 0; g < 2; ++g)
                ldsm_x4(bb[g], bB + (brow + g * 16) * 80 + kofb);
            // pass 1: Ah
#pragma unroll
            for (int mi = 0; mi < 2; ++mi)
#pragma unroll
                for (int ni = 0; ni < 4; ++ni)
                    mma16816(acc[mi][ni], ah[mi],
                             bb[ni >> 1][(ni & 1) * 2], bb[ni >> 1][(ni & 1) * 2 + 1]);
            // pass 2: Al (reuse regs)
#pragma unroll
            for (int mi = 0; mi < 2; ++mi)
                ldsm_x4(ah[mi], bAl + (arow + mi * 16) * 80 + kof);
#pragma unroll
            for (int mi = 0; mi < 2; ++mi)
#pragma unroll
                for (int ni = 0; ni < 4; ++ni)
                    mma16816(acc[mi][ni], ah[mi],
                             bb[ni >> 1][(ni & 1) * 2], bb[ni >> 1][(ni & 1) * 2 + 1]);
        }
    }

    // epilogue
    int third = 0;
    const float* bp = bias0;
    if (MODE == 2) {
        third = blockIdx.x >> 4;
        bp = (third == 0) ? bias0 : (third == 1) ? bias1 : bias2;
    }
    const float qscale = 0.125f * 1.44269504088896341f;

#pragma unroll
    for (int mi = 0; mi < 2; ++mi) {
#pragma unroll
        for (int ni = 0; ni < 4; ++ni) {
            int row = m0 + wm * 32 + mi * 16 + (lane >> 2);
            int col = n0 + wn * 32 + ni * 8 + (lane & 3) * 2;
            int cc  = col & 1023;
            float b0 = bp[cc], b1 = bp[cc + 1];
            float v0 = acc[mi][ni][0] + b0, v1 = acc[mi][ni][1] + b1;
            float v2 = acc[mi][ni][2] + b0, v3 = acc[mi][ni][3] + b1;
            if (MODE == 0) {
                *(float2*)(Cf + (size_t)row * Dq + cc)       = make_float2(v0, v1);
                *(float2*)(Cf + (size_t)(row + 8) * Dq + cc) = make_float2(v2, v3);
            } else if (third == 0) {
                v0 *= qscale; v1 *= qscale; v2 *= qscale; v3 *= qscale;
                __half h0 = __float2half(v0), h1 = __float2half(v1);
                __half h2 = __float2half(v2), h3 = __float2half(v3);
                *(__half2*)(Oqh + (size_t)row * Dq + cc)       = __halves2half2(h0, h1);
                *(__half2*)(Oqh + (size_t)(row + 8) * Dq + cc) = __halves2half2(h2, h3);
                *(__half2*)(Oql + (size_t)row * Dq + cc) =
                    __halves2half2(__float2half(v0 - __half2float(h0)),
                                   __float2half(v1 - __half2float(h1)));
                *(__half2*)(Oql + (size_t)(row + 8) * Dq + cc) =
                    __halves2half2(__float2half(v2 - __half2float(h2)),
                                   __float2half(v3 - __half2float(h3)));
            } else {
                __half* dst = (third == 1) ? Ok : Ov;
                *(__half2*)(dst + (size_t)row * Dq + cc) =
                    __halves2half2(__float2half(v0), __float2half(v1));
                *(__half2*)(dst + (size_t)(row + 8) * Dq + cc) =
                    __halves2half2(__float2half(v2), __float2half(v3));
            }
        }
    }
}

// ---------------------------------------------------------------------------
// fp16 flash attention (causal): Q fp16 hi/lo (2-pass QK), K/V single fp16,
// P fp16 hi/lo (2-pass PV). exp2 softmax, masked-warp skip, qt reversed.
// smem: Qh 18KB | 2 x (K 9216 | V 9216) = 54KB total.
// ---------------------------------------------------------------------------
#define ATT_SMEM (18432 + 2 * 18432)

__global__ void __launch_bounds__(256, 2)
attn_mma(const __half* __restrict__ Qh_g, const __half* __restrict__ Ql_g,
         const __half* __restrict__ K_g, const __half* __restrict__ V_g,
         __half* __restrict__ AOh_g, __half* __restrict__ AOl_g)
{
    extern __shared__ char smc[];
    const uint32_t smb = smem_u32(smc);
    const int t = threadIdx.x, lane = t & 31, w = t >> 5;
    const int qt = (int)gridDim.x - 1 - (int)blockIdx.x;
    const int b = blockIdx.y >> 4, h = blockIdx.y & 15;
    const size_t row0 = (size_t)b * Tq + qt * 128;

    const uint32_t SQH = smb;
    const uint32_t SKV = smb + 18432;    // 2 bufs x (K 9216 | V 9216)

    // prologue: Qh -> SQH, Ql staged into SKV
#pragma unroll
    for (int i = 0; i < 4; ++i) {
        int idx = t + i * 256, r = idx >> 3, s = idx & 7;
        size_t g = (row0 + r) * Dq + h * 64 + s * 8;
        cp_async16(SQH + r * 144 + s * 16, Qh_g + g);
        cp_async16(SKV + r * 144 + s * 16, Ql_g + g);
    }
    asm volatile("cp.async.commit_group;" ::: "memory");
    asm volatile("cp.async.wait_group 0;" ::: "memory");
    __syncthreads();

    const uint32_t arow = w * 16 + (lane & 15);
    const uint32_t aco  = (lane >> 4) * 8;
    uint32_t ql[4][4];
#pragma unroll
    for (int ks = 0; ks < 4; ++ks)
        ldsm_x4(ql[ks], SKV + arow * 144 + (ks * 16 + aco) * 2);
    __syncthreads();

    auto issue_kv = [&](int jt) {
        const uint32_t kb = SKV + (uint32_t)(jt & 1) * 18432;
#pragma unroll
        for (int i = 0; i < 4; ++i) {
            int idx = t + i * 256;
            int mat = idx >> 9, rem = idx & 511, r = rem >> 3, s = rem & 7;
            const __half* src = (mat == 0) ? K_g : V_g;
            size_t g = ((size_t)b * Tq + jt * 64 + r) * Dq + h * 64 + s * 8;
            cp_async16(kb + mat * 9216 + r * 144 + s * 16, src + g);
        }
        asm volatile("cp.async.commit_group;" ::: "memory");
    };

    float m0 = -1e30f, m1 = -1e30f, l0 = 0.f, l1 = 0.f;
    float oac[8][4];
#pragma unroll
    for (int ng = 0; ng < 8; ++ng)
#pragma unroll
        for (int k = 0; k < 4; ++k) oac[ng][k] = 0.f;

    const uint32_t krow = ((lane >> 4) & 1) * 8 + (lane & 7);
    const uint32_t kco  = ((lane >> 3) & 1) * 8;
    const uint32_t vrow = ((lane >> 3) & 1) * 8 + (lane & 7);
    const uint32_t vco  = ((lane >> 4) & 1) * 8;

    const int jtmax = 2 * qt + 1;
    issue_kv(0);

    for (int jt = 0; jt <= jtmax; ++jt) {
        asm volatile("cp.async.wait_group 0;" ::: "memory");
        __syncthreads();
        if (jt + 1 <= jtmax) issue_kv(jt + 1);

        if (jt * 64 > qt * 128 + w * 16 + 15) continue;   // fully masked

        const uint32_t SKH = SKV + (uint32_t)(jt & 1) * 18432;
        const uint32_t SVH = SKH + 9216;

        // ---- S = Q @ K^T (2-pass: qh + ql, K single)
        float sac[8][4];
#pragma unroll
        for (int ng = 0; ng < 8; ++ng)
#pragma unroll
            for (int k = 0; k < 4; ++k) sac[ng][k] = 0.f;

#pragma unroll
        for (int ks = 0; ks < 4; ++ks) {
            uint32_t qh[4];
            ldsm_x4(qh, SQH + arow * 144 + (ks * 16 + aco) * 2);
#pragma unroll
            for (int g = 0; g < 4; ++g) {
                uint32_t kb[4];
                ldsm_x4(kb, SKH + (g * 16 + krow) * 144 + (ks * 16 + kco) * 2);
                mma16816(sac[2*g],   qh,     kb[0], kb[1]);
                mma16816(sac[2*g+1], qh,     kb[2], kb[3]);
                mma16816(sac[2*g],   ql[ks], kb[0], kb[1]);
                mma16816(sac[2*g+1], ql[ks], kb[2], kb[3]);
            }
        }

        // ---- causal mask
        if (jt >= 2 * qt) {
            int q0 = qt * 128 + w * 16 + (lane >> 2);
#pragma unroll
            for (int ng = 0; ng < 8; ++ng) {
                int k0 = jt * 64 + ng * 8 + (lane & 3) * 2;
                if (k0     > q0)     sac[ng][0] = -1e30f;
                if (k0 + 1 > q0)     sac[ng][1] = -1e30f;
                if (k0     > q0 + 8) sac[ng][2] = -1e30f;
                if (k0 + 1 > q0 + 8) sac[ng][3] = -1e30f;
            }
        }

        // ---- row max + rescale
        float mx0 = -1e30f, mx1 = -1e30f;
#pragma unroll
        for (int ng = 0; ng < 8; ++ng) {
            mx0 = fmaxf(mx0, fmaxf(sac[ng][0], sac[ng][1]));
            mx1 = fmaxf(mx1, fmaxf(sac[ng][2], sac[ng][3]));
        }
        mx0 = fmaxf(mx0, __shfl_xor_sync(0xffffffffu, mx0, 1));
        mx0 = fmaxf(mx0, __shfl_xor_sync(0xffffffffu, mx0, 2));
        mx1 = fmaxf(mx1, __shfl_xor_sync(0xffffffffu, mx1, 1));
        mx1 = fmaxf(mx1, __shfl_xor_sync(0xffffffffu, mx1, 2));
        float mn0 = fmaxf(m0, mx0), mn1 = fmaxf(m1, mx1);
        float a0 = exp2f(m0 - mn0), a1 = exp2f(m1 - mn1);
        m0 = mn0; m1 = mn1;
#pragma unroll
        for (int ng = 0; ng < 8; ++ng) {
            oac[ng][0] *= a0; oac[ng][1] *= a0;
            oac[ng][2] *= a1; oac[ng][3] *= a1;
        }

        // ---- interleaved softmax + PV (2-pass: ph + pl, V single)
        float rs0 = 0.f, rs1 = 0.f;
#pragma unroll
        for (int ks = 0; ks < 4; ++ks) {
            float* p0 = sac[2*ks];
            float* p1 = sac[2*ks+1];
            p0[0] = exp2f(p0[0] - mn0); p0[1] = exp2f(p0[1] - mn0);
            p0[2] = exp2f(p0[2] - mn1); p0[3] = exp2f(p0[3] - mn1);
            p1[0] = exp2f(p1[0] - mn0); p1[1] = exp2f(p1[1] - mn0);
            p1[2] = exp2f(p1[2] - mn1); p1[3] = exp2f(p1[3] - mn1);
            rs0 += p0[0] + p0[1] + p1[0] + p1[1];
            rs1 += p0[2] + p0[3] + p1[2] + p1[3];

            uint32_t ph[4], pl[4];
            ph[0] = pack_h2(p0[0], p0[1]);
            ph[1] = pack_h2(p0[2], p0[3]);
            ph[2] = pack_h2(p1[0], p1[1]);
            ph[3] = pack_h2(p1[2], p1[3]);
            {
                __half2 t0 = *(__half2*)&ph[0];
                __half2 t1 = *(__half2*)&ph[1];
                __half2 t2 = *(__half2*)&ph[2];
                __half2 t3 = *(__half2*)&ph[3];
                pl[0] = pack_h2(p0[0] - __half2float(t0.x), p0[1] - __half2float(t0.y));
                pl[1] = pack_h2(p0[2] - __half2float(t1.x), p0[3] - __half2float(t1.y));
                pl[2] = pack_h2(p1[0] - __half2float(t2.x), p1[1] - __half2float(t2.y));
                pl[3] = pack_h2(p1[2] - __half2float(t3.x), p1[3] - __half2float(t3.y));
            }
#pragma unroll
            for (int g = 0; g < 4; ++g) {
                uint32_t vb[4];
                ldsm_x4_t(vb, SVH + (ks * 16 + vrow) * 144 + (g * 16 + vco) * 2);
                mma16816(oac[2*g],   ph, vb[0], vb[1]);
                mma16816(oac[2*g+1], ph, vb[2], vb[3]);
                mma16816(oac[2*g],   pl, vb[0], vb[1]);
                mma16816(oac[2*g+1], pl, vb[2], vb[3]);
            }
        }

        rs0 += __shfl_xor_sync(0xffffffffu, rs0, 1);
        rs0 += __shfl_xor_sync(0xffffffffu, rs0, 2);
        rs1 += __shfl_xor_sync(0xffffffffu, rs1, 1);
        rs1 += __shfl_xor_sync(0xffffffffu, rs1, 2);
        l0 = l0 * a0 + rs0; l1 = l1 * a1 + rs1;
    }

    // ---- epilogue: normalize + fp16 hi/lo AO
    float i0 = 1.f / l0, i1 = 1.f / l1;
    size_t gr0 = row0 + w * 16 + (lane >> 2);
#pragma unroll
    for (int ng = 0; ng < 8; ++ng) {
        int col = h * 64 + ng * 8 + (lane & 3) * 2;
        float v0 = oac[ng][0] * i0, v1 = oac[ng][1] * i0;
        float v2 = oac[ng][2] * i1, v3 = oac[ng][3] * i1;
        __half h0 = __float2half(v0), h1 = __float2half(v1);
        __half h2 = __float2half(v2), h3 = __float2half(v3);
        *(__half2*)(AOh_g + gr0 * Dq + col)       = __halves2half2(h0, h1);
        *(__half2*)(AOh_g + (gr0 + 8) * Dq + col) = __halves2half2(h2, h3);
        *(__half2*)(AOl_g + gr0 * Dq + col) =
            __halves2half2(__float2half(v0 - __half2float(h0)),
                           __float2half(v1 - __half2float(h1)));
        *(__half2*)(AOl_g + (gr0 + 8) * Dq + col) =
            __halves2half2(__float2half(v2 - __half2float(h2)),
                           __float2half(v3 - __half2float(h3)));
    }
}

// ---------------------------------------------------------------------------
extern "C" void kernel_launch(void* const* d_in, const int* in_sizes, int n_in,
                              void* d_out, int out_size)
{
    const float* x  = (const float*)d_in[0];
    const float* Wq = (const float*)d_in[2];
    const float* bq = (const float*)d_in[3];
    const float* Wk = (const float*)d_in[4];
    const float* bk = (const float*)d_in[5];
    const float* Wv = (const float*)d_in[6];
    const float* bv = (const float*)d_in[7];
    const float* Wo = (const float*)d_in[8];
    const float* bo = (const float*)d_in[9];
    float* out = (float*)d_out;

    __half *ahi, *alo, *wm, *qh, *qlp, *kp, *vp, *aoh, *aol;
    cudaGetSymbolAddress((void**)&ahi, g_Ahi);
    cudaGetSymbolAddress((void**)&alo, g_Alo);
    cudaGetSymbolAddress((void**)&wm,  g_W);
    cudaGetSymbolAddress((void**)&qh,  g_Qh);
    cudaGetSymbolAddress((void**)&qlp, g_Ql);
    cudaGetSymbolAddress((void**)&kp,  g_K);
    cudaGetSymbolAddress((void**)&vp,  g_V);
    cudaGetSymbolAddress((void**)&aoh, g_AOh);
    cudaGetSymbolAddress((void**)&aol, g_AOl);

    cudaFuncSetAttribute(gemm_mma<0>, cudaFuncAttributeMaxDynamicSharedMemorySize, GEMM_SMEM);
    cudaFuncSetAttribute(gemm_mma<2>, cudaFuncAttributeMaxDynamicSharedMemorySize, GEMM_SMEM);
    cudaFuncSetAttribute(attn_mma, cudaFuncAttributeMaxDynamicSharedMemorySize, ATT_SMEM);

    const int NPROJ = Mq * Dq;

    split_kernel<<<NPROJ / 1024, 256>>>(x, ahi, alo, NPROJ);
    dim3 tsg(32, 32, 4), tsb(32, 8);
    transpose4_kernel<<<tsg, tsb>>>(Wq, Wk, Wv, Wo, wm);

    // merged QKV projection (N = 3072)
    dim3 qkvgrid(3 * Dq / 64, Mq / 64);    // (48, 64)
    gemm_mma<2><<<qkvgrid, 128, GEMM_SMEM>>>(ahi, alo, wm,
                                             bq, bk, bv, nullptr,
                                             qh, qlp, kp, vp);

    dim3 agrid(Tq / 128, Bq * Hq);
    attn_mma<<<agrid, 256, ATT_SMEM>>>(qh, qlp, kp, vp, aoh, aol);

    dim3 ogrid(Dq / 64, Mq / 64);          // (16, 64)
    gemm_mma<0><<<ogrid, 128, GEMM_SMEM>>>(aoh, aol, wm + 3 * (size_t)Dq * Dq,
                                           bo, nullptr, nullptr, out,
                                           nullptr, nullptr, nullptr, nullptr);
}

// round 17
// speedup vs baseline: 1.5554x; 1.0803x over previous
#include <cuda_runtime.h>
#include <cuda_fp16.h>
#include <cstdint>
#include <cstddef>

#define Bq   2
#define Tq   2048
#define Dq   1024
#define Hq   16
#define DKq  64
#define Mq   (Bq*Tq)     // 4096

// ---------------- scratch (device globals: allocation-free) ----------------
__device__ __align__(16) __half g_Ahi[Mq * Dq];
__device__ __align__(16) __half g_Alo[Mq * Dq];
__device__ __align__(16) __half g_W[4][Dq * Dq];     // transposed [n][k], single fp16
__device__ __align__(16) __half g_Qh[Mq * Dq];
__device__ __align__(16) __half g_Ql[Mq * Dq];
__device__ __align__(16) __half g_K[Mq * Dq];
__device__ __align__(16) __half g_V[Mq * Dq];
__device__ __align__(16) __half g_AOh[Mq * Dq];
__device__ __align__(16) __half g_AOl[Mq * Dq];

// ---------------------------------------------------------------------------
__device__ __forceinline__ uint32_t smem_u32(const void* p) {
    uint32_t a;
    asm("{ .reg .u64 t; cvta.to.shared.u64 t, %1; cvt.u32.u64 %0, t; }" : "=r"(a) : "l"(p));
    return a;
}
__device__ __forceinline__ void cp_async16(uint32_t saddr, const void* gaddr) {
    asm volatile("cp.async.cg.shared.global [%0], [%1], 16;" :: "r"(saddr), "l"(gaddr));
}
__device__ __forceinline__ void ldsm_x4(uint32_t* r, uint32_t saddr) {
    asm volatile("ldmatrix.sync.aligned.m8n8.x4.shared.b16 {%0,%1,%2,%3}, [%4];"
                 : "=r"(r[0]), "=r"(r[1]), "=r"(r[2]), "=r"(r[3]) : "r"(saddr));
}
__device__ __forceinline__ void ldsm_x4_t(uint32_t* r, uint32_t saddr) {
    asm volatile("ldmatrix.sync.aligned.m8n8.x4.trans.shared.b16 {%0,%1,%2,%3}, [%4];"
                 : "=r"(r[0]), "=r"(r[1]), "=r"(r[2]), "=r"(r[3]) : "r"(saddr));
}
__device__ __forceinline__ void mma16816(float* d, const uint32_t* a, uint32_t b0, uint32_t b1) {
    asm volatile(
        "mma.sync.aligned.m16n8k16.row.col.f32.f16.f16.f32 "
        "{%0,%1,%2,%3}, {%4,%5,%6,%7}, {%8,%9}, {%0,%1,%2,%3};"
        : "+f"(d[0]), "+f"(d[1]), "+f"(d[2]), "+f"(d[3])
        : "r"(a[0]), "r"(a[1]), "r"(a[2]), "r"(a[3]), "r"(b0), "r"(b1));
}
__device__ __forceinline__ uint32_t pack_h2(float a, float b) {
    __half2 t = __halves2half2(__float2half(a), __float2half(b));
    return *(uint32_t*)&t;
}

// ---------------------------------------------------------------------------
// fp32 -> fp16 hi/lo split
__global__ void split_kernel(const float* __restrict__ src,
                             __half* __restrict__ hi,
                             __half* __restrict__ lo, int n)
{
    int i = (blockIdx.x * blockDim.x + threadIdx.x) * 4;
    if (i >= n) return;
    float4 v = *(const float4*)(src + i);
    __half h0 = __float2half(v.x), h1 = __float2half(v.y);
    __half h2 = __float2half(v.z), h3 = __float2half(v.w);
    __half l0 = __float2half(v.x - __half2float(h0));
    __half l1 = __float2half(v.y - __half2float(h1));
    __half l2 = __float2half(v.z - __half2float(h2));
    __half l3 = __float2half(v.w - __half2float(h3));
    ((__half2*)(hi + i))[0] = __halves2half2(h0, h1);
    ((__half2*)(hi + i))[1] = __halves2half2(h2, h3);
    ((__half2*)(lo + i))[0] = __halves2half2(l0, l1);
    ((__half2*)(lo + i))[1] = __halves2half2(l2, l3);
}

// all 4 weights -> transposed single fp16
__global__ void transpose4_kernel(const float* __restrict__ W0,
                                  const float* __restrict__ W1,
                                  const float* __restrict__ W2,
                                  const float* __restrict__ W3,
                                  __half* __restrict__ dst)
{
    __shared__ float tile[32][33];
    const int wsel = blockIdx.z;
    const float* W = (wsel == 0) ? W0 : (wsel == 1) ? W1 : (wsel == 2) ? W2 : W3;
    __half* hp = dst + (size_t)wsel * Dq * Dq;
    int n0 = blockIdx.x * 32, k0 = blockIdx.y * 32;
    int x = threadIdx.x, y = threadIdx.y;
#pragma unroll
    for (int r = 0; r < 32; r += 8)
        tile[y + r][x] = W[(size_t)(k0 + y + r) * Dq + n0 + x];
    __syncthreads();
#pragma unroll
    for (int r = 0; r < 32; r += 8)
        hp[(size_t)(n0 + y + r) * Dq + k0 + x] = __float2half(tile[x][y + r]);
}

// ---------------------------------------------------------------------------
// fp16 2-pass GEMM: C = (Ah + Al) @ B^T (+bias).  B single fp16.
// CTA 64x64, 4 warps (32x32 warp tile), BK=32, 2-stage cp.async, occ 5.
// ---------------------------------------------------------------------------
#define GSTAGE 15360
#define GEMM_SMEM (2 * GSTAGE)

template<int MODE>
__global__ void __launch_bounds__(128, 5)
gemm_mma(const __half* __restrict__ Ah, const __half* __restrict__ Al,
         const __half* __restrict__ B,
         const float* __restrict__ bias0, const float* __restrict__ bias1,
         const float* __restrict__ bias2,
         float* __restrict__ Cf,
         __half* __restrict__ Oqh, __half* __restrict__ Oql,
         __half* __restrict__ Ok,  __half* __restrict__ Ov)
{
    extern __shared__ char smc[];
    const uint32_t smb = smem_u32(smc);
    const int t = threadIdx.x, lane = t & 31, wid = t >> 5;
    const int wm = wid >> 1, wn = wid & 1;
    const int m0 = blockIdx.y * 64, n0 = blockIdx.x * 64;

    float acc[2][4][4];
#pragma unroll
    for (int i = 0; i < 2; i++)
#pragma unroll
        for (int j = 0; j < 4; j++)
#pragma unroll
            for (int k = 0; k < 4; k++) acc[i][j][k] = 0.f;

    const __half* Amats[2] = { Ah + (size_t)m0 * Dq, Al + (size_t)m0 * Dq };
    const __half* Bmat = B + (size_t)n0 * Dq;

    auto issue = [&](int c) {
        const uint32_t base = smb + (uint32_t)(c & 1) * GSTAGE;
        const int kk = c * 32;
#pragma unroll
        for (int m = 0; m < 2; ++m) {
            const __half* s = Amats[m] + kk;
#pragma unroll
            for (int it = 0; it < 2; ++it) {
                int idx = t + it * 128;
                int r = idx >> 2, seg = idx & 3;
                cp_async16(base + m * 5120 + r * 80 + seg * 16,
                           s + (size_t)r * Dq + seg * 8);
            }
        }
        {
            const __half* s = Bmat + kk;
#pragma unroll
            for (int it = 0; it < 2; ++it) {
                int idx = t + it * 128;
                int r = idx >> 2, seg = idx & 3;
                cp_async16(base + 10240 + r * 80 + seg * 16,
                           s + (size_t)r * Dq + seg * 8);
            }
        }
        asm volatile("cp.async.commit_group;" ::: "memory");
    };

    issue(0);

    const int arow = wm * 32 + (lane & 15);
    const int aco  = (lane >> 4) * 8;
    const int brow = wn * 32 + ((lane >> 4) & 1) * 8 + (lane & 7);
    const int bco  = ((lane >> 3) & 1) * 8;

    for (int c = 0; c < 32; ++c) {
        asm volatile("cp.async.wait_group 0;" ::: "memory");
        __syncthreads();
        if (c + 1 < 32) issue(c + 1);

        const uint32_t bAh = smb + (uint32_t)(c & 1) * GSTAGE;
        const uint32_t bAl = bAh + 5120, bB = bAh + 10240;

#pragma unroll
        for (int ks = 0; ks < 2; ++ks) {
            const int kof  = (ks * 16 + aco) * 2;
            const int kofb = (ks * 16 + bco) * 2;
            uint32_t ah[2][4], bb[2][4];
#pragma unroll
            for (int mi = 0; mi < 2; ++mi)
                ldsm_x4(ah[mi], bAh + (arow + mi * 16) * 80 + kof);
#pragma unroll
            for (int g = 0; g < 2; ++g)
                ldsm_x4(bb[g], bB + (brow + g * 16) * 80 + kofb);
#pragma unroll
            for (int mi = 0; mi < 2; ++mi)
#pragma unroll
                for (int ni = 0; ni < 4; ++ni)
                    mma16816(acc[mi][ni], ah[mi],
                             bb[ni >> 1][(ni & 1) * 2], bb[ni >> 1][(ni & 1) * 2 + 1]);
#pragma unroll
            for (int mi = 0; mi < 2; ++mi)
                ldsm_x4(ah[mi], bAl + (arow + mi * 16) * 80 + kof);
#pragma unroll
            for (int mi = 0; mi < 2; ++mi)
#pragma unroll
                for (int ni = 0; ni < 4; ++ni)
                    mma16816(acc[mi][ni], ah[mi],
                             bb[ni >> 1][(ni & 1) * 2], bb[ni >> 1][(ni & 1) * 2 + 1]);
        }
    }

    // epilogue
    int third = 0;
    const float* bp = bias0;
    if (MODE == 2) {
        third = blockIdx.x >> 4;
        bp = (third == 0) ? bias0 : (third == 1) ? bias1 : bias2;
    }
    const float qscale = 0.125f * 1.44269504088896341f;

#pragma unroll
    for (int mi = 0; mi < 2; ++mi) {
#pragma unroll
        for (int ni = 0; ni < 4; ++ni) {
            int row = m0 + wm * 32 + mi * 16 + (lane >> 2);
            int col = n0 + wn * 32 + ni * 8 + (lane & 3) * 2;
            int cc  = col & 1023;
            float b0 = bp[cc], b1 = bp[cc + 1];
            float v0 = acc[mi][ni][0] + b0, v1 = acc[mi][ni][1] + b1;
            float v2 = acc[mi][ni][2] + b0, v3 = acc[mi][ni][3] + b1;
            if (MODE == 0) {
                *(float2*)(Cf + (size_t)row * Dq + cc)       = make_float2(v0, v1);
                *(float2*)(Cf + (size_t)(row + 8) * Dq + cc) = make_float2(v2, v3);
            } else if (third == 0) {
                v0 *= qscale; v1 *= qscale; v2 *= qscale; v3 *= qscale;
                __half h0 = __float2half(v0), h1 = __float2half(v1);
                __half h2 = __float2half(v2), h3 = __float2half(v3);
                *(__half2*)(Oqh + (size_t)row * Dq + cc)       = __halves2half2(h0, h1);
                *(__half2*)(Oqh + (size_t)(row + 8) * Dq + cc) = __halves2half2(h2, h3);
                *(__half2*)(Oql + (size_t)row * Dq + cc) =
                    __halves2half2(__float2half(v0 - __half2float(h0)),
                                   __float2half(v1 - __half2float(h1)));
                *(__half2*)(Oql + (size_t)(row + 8) * Dq + cc) =
                    __halves2half2(__float2half(v2 - __half2float(h2)),
                                   __float2half(v3 - __half2float(h3)));
            } else {
                __half* dst = (third == 1) ? Ok : Ov;
                *(__half2*)(dst + (size_t)row * Dq + cc) =
                    __halves2half2(__float2half(v0), __float2half(v1));
                *(__half2*)(dst + (size_t)(row + 8) * Dq + cc) =
                    __halves2half2(__float2half(v2), __float2half(v3));
            }
        }
    }
}

// ---------------------------------------------------------------------------
// fp16 flash attention (causal): Q fp16 hi/lo (2-pass QK), K/V single fp16,
// P single fp16 (1-pass PV). exp2 softmax, masked-warp skip, qt reversed.
// ---------------------------------------------------------------------------
#define ATT_SMEM (18432 + 2 * 18432)

__global__ void __launch_bounds__(256, 2)
attn_mma(const __half* __restrict__ Qh_g, const __half* __restrict__ Ql_g,
         const __half* __restrict__ K_g, const __half* __restrict__ V_g,
         __half* __restrict__ AOh_g, __half* __restrict__ AOl_g)
{
    extern __shared__ char smc[];
    const uint32_t smb = smem_u32(smc);
    const int t = threadIdx.x, lane = t & 31, w = t >> 5;
    const int qt = (int)gridDim.x - 1 - (int)blockIdx.x;
    const int b = blockIdx.y >> 4, h = blockIdx.y & 15;
    const size_t row0 = (size_t)b * Tq + qt * 128;

    const uint32_t SQH = smb;
    const uint32_t SKV = smb + 18432;

#pragma unroll
    for (int i = 0; i < 4; ++i) {
        int idx = t + i * 256, r = idx >> 3, s = idx & 7;
        size_t g = (row0 + r) * Dq + h * 64 + s * 8;
        cp_async16(SQH + r * 144 + s * 16, Qh_g + g);
        cp_async16(SKV + r * 144 + s * 16, Ql_g + g);
    }
    asm volatile("cp.async.commit_group;" ::: "memory");
    asm volatile("cp.async.wait_group 0;" ::: "memory");
    __syncthreads();

    const uint32_t arow = w * 16 + (lane & 15);
    const uint32_t aco  = (lane >> 4) * 8;
    uint32_t ql[4][4];
#pragma unroll
    for (int ks = 0; ks < 4; ++ks)
        ldsm_x4(ql[ks], SKV + arow * 144 + (ks * 16 + aco) * 2);
    __syncthreads();

    auto issue_kv = [&](int jt) {
        const uint32_t kb = SKV + (uint32_t)(jt & 1) * 18432;
#pragma unroll
        for (int i = 0; i < 4; ++i) {
            int idx = t + i * 256;
            int mat = idx >> 9, rem = idx & 511, r = rem >> 3, s = rem & 7;
            const __half* src = (mat == 0) ? K_g : V_g;
            size_t g = ((size_t)b * Tq + jt * 64 + r) * Dq + h * 64 + s * 8;
            cp_async16(kb + mat * 9216 + r * 144 + s * 16, src + g);
        }
        asm volatile("cp.async.commit_group;" ::: "memory");
    };

    float m0 = -1e30f, m1 = -1e30f, l0 = 0.f, l1 = 0.f;
    float oac[8][4];
#pragma unroll
    for (int ng = 0; ng < 8; ++ng)
#pragma unroll
        for (int k = 0; k < 4; ++k) oac[ng][k] = 0.f;

    const uint32_t krow = ((lane >> 4) & 1) * 8 + (lane & 7);
    const uint32_t kco  = ((lane >> 3) & 1) * 8;
    const uint32_t vrow = ((lane >> 3) & 1) * 8 + (lane & 7);
    const uint32_t vco  = ((lane >> 4) & 1) * 8;

    const int jtmax = 2 * qt + 1;
    issue_kv(0);

    for (int jt = 0; jt <= jtmax; ++jt) {
        asm volatile("cp.async.wait_group 0;" ::: "memory");
        __syncthreads();
        if (jt + 1 <= jtmax) issue_kv(jt + 1);

        if (jt * 64 > qt * 128 + w * 16 + 15) continue;   // fully masked

        const uint32_t SKH = SKV + (uint32_t)(jt & 1) * 18432;
        const uint32_t SVH = SKH + 9216;

        // ---- S = Q @ K^T (2-pass: qh + ql, K single)
        float sac[8][4];
#pragma unroll
        for (int ng = 0; ng < 8; ++ng)
#pragma unroll
            for (int k = 0; k < 4; ++k) sac[ng][k] = 0.f;

#pragma unroll
        for (int ks = 0; ks < 4; ++ks) {
            uint32_t qh[4];
            ldsm_x4(qh, SQH + arow * 144 + (ks * 16 + aco) * 2);
#pragma unroll
            for (int g = 0; g < 4; ++g) {
                uint32_t kb[4];
                ldsm_x4(kb, SKH + (g * 16 + krow) * 144 + (ks * 16 + kco) * 2);
                mma16816(sac[2*g],   qh,     kb[0], kb[1]);
                mma16816(sac[2*g+1], qh,     kb[2], kb[3]);
                mma16816(sac[2*g],   ql[ks], kb[0], kb[1]);
                mma16816(sac[2*g+1], ql[ks], kb[2], kb[3]);
            }
        }

        // ---- causal mask
        if (jt >= 2 * qt) {
            int q0 = qt * 128 + w * 16 + (lane >> 2);
#pragma unroll
            for (int ng = 0; ng < 8; ++ng) {
                int k0 = jt * 64 + ng * 8 + (lane & 3) * 2;
                if (k0     > q0)     sac[ng][0] = -1e30f;
                if (k0 + 1 > q0)     sac[ng][1] = -1e30f;
                if (k0     > q0 + 8) sac[ng][2] = -1e30f;
                if (k0 + 1 > q0 + 8) sac[ng][3] = -1e30f;
            }
        }

        // ---- row max + rescale
        float mx0 = -1e30f, mx1 = -1e30f;
#pragma unroll
        for (int ng = 0; ng < 8; ++ng) {
            mx0 = fmaxf(mx0, fmaxf(sac[ng][0], sac[ng][1]));
            mx1 = fmaxf(mx1, fmaxf(sac[ng][2], sac[ng][3]));
        }
        mx0 = fmaxf(mx0, __shfl_xor_sync(0xffffffffu, mx0, 1));
        mx0 = fmaxf(mx0, __shfl_xor_sync(0xffffffffu, mx0, 2));
        mx1 = fmaxf(mx1, __shfl_xor_sync(0xffffffffu, mx1, 1));
        mx1 = fmaxf(mx1, __shfl_xor_sync(0xffffffffu, mx1, 2));
        float mn0 = fmaxf(m0, mx0), mn1 = fmaxf(m1, mx1);
        float a0 = exp2f(m0 - mn0), a1 = exp2f(m1 - mn1);
        m0 = mn0; m1 = mn1;
#pragma unroll
        for (int ng = 0; ng < 8; ++ng) {
            oac[ng][0] *= a0; oac[ng][1] *= a0;
            oac[ng][2] *= a1; oac[ng][3] *= a1;
        }

        // ---- interleaved softmax + PV (1-pass: P single fp16)
        float rs0 = 0.f, rs1 = 0.f;
#pragma unroll
        for (int ks = 0; ks < 4; ++ks) {
            float* p0 = sac[2*ks];
            float* p1 = sac[2*ks+1];
            p0[0] = exp2f(p0[0] - mn0); p0[1] = exp2f(p0[1] - mn0);
            p0[2] = exp2f(p0[2] - mn1); p0[3] = exp2f(p0[3] - mn1);
            p1[0] = exp2f(p1[0] - mn0); p1[1] = exp2f(p1[1] - mn0);
            p1[2] = exp2f(p1[2] - mn1); p1[3] = exp2f(p1[3] - mn1);
            rs0 += p0[0] + p0[1] + p1[0] + p1[1];
            rs1 += p0[2] + p0[3] + p1[2] + p1[3];

            uint32_t ph[4];
            ph[0] = pack_h2(p0[0], p0[1]);
            ph[1] = pack_h2(p0[2], p0[3]);
            ph[2] = pack_h2(p1[0], p1[1]);
            ph[3] = pack_h2(p1[2], p1[3]);
#pragma unroll
            for (int g = 0; g < 4; ++g) {
                uint32_t vb[4];
                ldsm_x4_t(vb, SVH + (ks * 16 + vrow) * 144 + (g * 16 + vco) * 2);
                mma16816(oac[2*g],   ph, vb[0], vb[1]);
                mma16816(oac[2*g+1], ph, vb[2], vb[3]);
            }
        }

        rs0 += __shfl_xor_sync(0xffffffffu, rs0, 1);
        rs0 += __shfl_xor_sync(0xffffffffu, rs0, 2);
        rs1 += __shfl_xor_sync(0xffffffffu, rs1, 1);
        rs1 += __shfl_xor_sync(0xffffffffu, rs1, 2);
        l0 = l0 * a0 + rs0; l1 = l1 * a1 + rs1;
    }

    // ---- epilogue: normalize + fp16 hi/lo AO
    float i0 = 1.f / l0, i1 = 1.f / l1;
    size_t gr0 = row0 + w * 16 + (lane >> 2);
#pragma unroll
    for (int ng = 0; ng < 8; ++ng) {
        int col = h * 64 + ng * 8 + (lane & 3) * 2;
        float v0 = oac[ng][0] * i0, v1 = oac[ng][1] * i0;
        float v2 = oac[ng][2] * i1, v3 = oac[ng][3] * i1;
        __half h0 = __float2half(v0), h1 = __float2half(v1);
        __half h2 = __float2half(v2), h3 = __float2half(v3);
        *(__half2*)(AOh_g + gr0 * Dq + col)       = __halves2half2(h0, h1);
        *(__half2*)(AOh_g + (gr0 + 8) * Dq + col) = __halves2half2(h2, h3);
        *(__half2*)(AOl_g + gr0 * Dq + col) =
            __halves2half2(__float2half(v0 - __half2float(h0)),
                           __float2half(v1 - __half2float(h1)));
        *(__half2*)(AOl_g + (gr0 + 8) * Dq + col) =
            __halves2half2(__float2half(v2 - __half2float(h2)),
                           __float2half(v3 - __half2float(h3)));
    }
}

// ---------------------------------------------------------------------------
extern "C" void kernel_launch(void* const* d_in, const int* in_sizes, int n_in,
                              void* d_out, int out_size)
{
    const float* x  = (const float*)d_in[0];
    const float* Wq = (const float*)d_in[2];
    const float* bq = (const float*)d_in[3];
    const float* Wk = (const float*)d_in[4];
    const float* bk = (const float*)d_in[5];
    const float* Wv = (const float*)d_in[6];
    const float* bv = (const float*)d_in[7];
    const float* Wo = (const float*)d_in[8];
    const float* bo = (const float*)d_in[9];
    float* out = (float*)d_out;

    __half *ahi, *alo, *wm, *qh, *qlp, *kp, *vp, *aoh, *aol;
    cudaGetSymbolAddress((void**)&ahi, g_Ahi);
    cudaGetSymbolAddress((void**)&alo, g_Alo);
    cudaGetSymbolAddress((void**)&wm,  g_W);
    cudaGetSymbolAddress((void**)&qh,  g_Qh);
    cudaGetSymbolAddress((void**)&qlp, g_Ql);
    cudaGetSymbolAddress((void**)&kp,  g_K);
    cudaGetSymbolAddress((void**)&vp,  g_V);
    cudaGetSymbolAddress((void**)&aoh, g_AOh);
    cudaGetSymbolAddress((void**)&aol, g_AOl);

    cudaFuncSetAttribute(gemm_mma<0>, cudaFuncAttributeMaxDynamicSharedMemorySize, GEMM_SMEM);
    cudaFuncSetAttribute(gemm_mma<2>, cudaFuncAttributeMaxDynamicSharedMemorySize, GEMM_SMEM);
    cudaFuncSetAttribute(attn_mma, cudaFuncAttributeMaxDynamicSharedMemorySize, ATT_SMEM);

    const int NPROJ = Mq * Dq;

    split_kernel<<<NPROJ / 1024, 256>>>(x, ahi, alo, NPROJ);
    dim3 tsg(32, 32, 4), tsb(32, 8);
    transpose4_kernel<<<tsg, tsb>>>(Wq, Wk, Wv, Wo, wm);

    dim3 qkvgrid(3 * Dq / 64, Mq / 64);    // (48, 64)
    gemm_mma<2><<<qkvgrid, 128, GEMM_SMEM>>>(ahi, alo, wm,
                                             bq, bk, bv, nullptr,
                                             qh, qlp, kp, vp);

    dim3 agrid(Tq / 128, Bq * Hq);
    attn_mma<<<agrid, 256, ATT_SMEM>>>(qh, qlp, kp, vp, aoh, aol);

    dim3 ogrid(Dq / 64, Mq / 64);          // (16, 64)
    gemm_mma<0><<<ogrid, 128, GEMM_SMEM>>>(aoh, aol, wm + 3 * (size_t)Dq * Dq,
                                           bo, nullptr, nullptr, out,
                                           nullptr, nullptr, nullptr, nullptr);
}